// round 14
// baseline (speedup 1.0000x reference)
#include <cuda_runtime.h>
#include <cuda_bf16.h>
#include <cstdint>

#define Bb   256
#define Dd   256
#define Vv   2000
#define VTt  10000
#define OPTo 16
#define SEQs 10
#define SRCs 40
#define G3   768
#define GSTEP 64
#define RPB   4
#define THR   512
#define ALMAX 20

#define OFF_OPT  164352
#define OFF_TOPO 168448
#define OFF_EX   178688

typedef unsigned long long ull;

// ---------------- device scratch ----------------
__device__ float d_ts[Bb*Dd];
__device__ float d_lse[SEQs*Bb];
__device__ int   d_acnt[SEQs*Bb];
__device__ int   d_alist[SEQs*Bb*ALMAX];
__device__ float d_av[SEQs*Bb*ALMAX];
__device__ int   d_sym[Bb*SEQs];
__device__ float d_WsymT[(size_t)Vv*Dd];
__device__ __nv_bfloat16 d_Ahi[Bb*SEQs*2*Dd];
__device__ __nv_bfloat16 d_WhiT[(size_t)VTt*2*Dd];

__device__ __forceinline__ unsigned f2mono(float f) {
    unsigned u = __float_as_uint(f);
    return (u & 0x80000000u) ? ~u : (u | 0x80000000u);
}

// packed f32x2 helpers (sm_103a)
#define FMA2(d, a, b) asm("fma.rn.f32x2 %0, %1, %2, %0;" : "+l"(d) : "l"(a), "l"(b))
__device__ __forceinline__ ull pk2(float x, float y) {
    ull r;
    asm("mov.b64 %0, {%1,%2};" : "=l"(r) : "f"(x), "f"(y));
    return r;
}
__device__ __forceinline__ float2 up2(ull v) {
    float2 r;
    asm("mov.b64 {%0,%1}, %2;" : "=f"(r.x), "=f"(r.y) : "l"(v));
    return r;
}

// ---------------- allowed-symbol lists per (t,b) ----------------
__global__ void k_alist(const int* __restrict__ gg) {
    int tb = blockIdx.x;                 // t*Bb + b
    int t = tb / Bb, b = tb % Bb;
    int lane = threadIdx.x;              // 32
    int sym = 0, m = 0;
    if (lane < OPTo) {
        int base = ((b*OPTo + lane)*4)*SEQs + t;
        sym = gg[base];
        m   = gg[base + 3*SEQs];
    }
    bool valid = (lane < OPTo) && m && (sym > 0);
    unsigned w0 = __ballot_sync(0xffffffffu, (lane < OPTo) && m && (sym == 0));
    unsigned vm = __ballot_sync(0xffffffffu, valid);
    // CONVERGENT match: inactive lanes use unique sentinel keys
    int key = valid ? sym : (0x40000000 + lane);
    unsigned grp = __match_any_sync(0xffffffffu, key);
    bool keep = valid && (((grp & vm) & ((1u << lane) - 1u)) == 0u);
    unsigned km = __ballot_sync(0xffffffffu, keep);
    int c0 = w0 ? 1 : 0;
    int cnt = c0 + __popc(km);
    int pos = c0 + __popc(km & ((1u << lane) - 1u));
    int* lst = d_alist + tb*ALMAX;
    if (lane == 0) {
        d_acnt[tb] = cnt;
        if (w0) lst[0] = 0;
    }
    if (keep) lst[pos] = sym;
    // zero-pad so k_steps main path can load unconditionally
    for (int i = cnt + lane; i < ALMAX; i += 32) lst[i] = 0;
}

// ---------------- copy small outputs ----------------
__global__ void k_copy(const int* __restrict__ lhs, const int* __restrict__ lmask,
                       const int* __restrict__ gg, float* __restrict__ out) {
    for (int i = blockIdx.x*blockDim.x + threadIdx.x; i < OFF_OPT; i += gridDim.x*blockDim.x) {
        if (i < 256)       out[i] = (float)lhs[i];
        else if (i < 512)  out[i] = (float)lmask[i-256];
        else               out[i] = (float)gg[i-512];
    }
}

// ---------------- prep W: Wtok transpose to (VT,512) bf16 ----------------
__global__ void k_prepW(const float* __restrict__ Wtok) {
    __shared__ float tile[32][33];
    int bi = blockIdx.x;
    int tid = threadIdx.x;
    int tx = tid & 31, ty = tid >> 5;
    int n0 = (bi % 313)*32, k0 = (bi / 313)*32;
    #pragma unroll
    for (int i=0;i<4;i++) {
        int k = k0 + ty + i*8, n = n0 + tx;
        tile[ty+i*8][tx] = (n < VTt) ? Wtok[(size_t)k*VTt + n] : 0.f;
    }
    __syncthreads();
    #pragma unroll
    for (int i=0;i<4;i++) {
        int n = n0 + ty + i*8, k = k0 + tx;
        if (n < VTt)
            d_WhiT[(size_t)n*512 + k] = __float2bfloat16(tile[tx][ty+i*8]);
    }
}

// ---------------- prep: Wsym transpose to (Vv,256) fp32 ----------------
__global__ void k_prepWT(const float* __restrict__ Wsym) {
    __shared__ float tile[32][33];
    int n0 = blockIdx.x*32, k0 = blockIdx.y*32;
    int tx = threadIdx.x, ty = threadIdx.y;   // 32x8
    #pragma unroll
    for (int i=0;i<4;i++) {
        int k = k0 + ty + i*8, n = n0 + tx;
        tile[ty+i*8][tx] = (n < Vv) ? Wsym[(size_t)k*Vv + n] : 0.f;
    }
    __syncthreads();
    #pragma unroll
    for (int i=0;i<4;i++) {
        int n = n0 + ty + i*8, k = k0 + tx;
        if (n < Vv)
            d_WsymT[(size_t)n*Dd + k] = tile[tx][ty+i*8];
    }
}

// ============================================================================
// k_steps: 64 blocks x 4 batches, 512 threads, pipelined f32x2 streaming GEMMs.
// Logits computed ONLY at allowed columns (sparse masked-logit path).
// ============================================================================
#define SM_MEM   0            // 40960
#define SM_GH    40960        // 3072
#define SM_GX    44032        // 3072   (also soa-phase scratch)
#define SM_TS0   47104        // 1024
#define SM_TS    48128        // 1024
#define SM_XP    49152        // 1024  packed [k][4]
#define SM_CATP  50176        // 2048  packed [k][4]
#define SM_SOAP  52224        // 1024  packed [k][4]
#define SM_H     53248        // 1024  unpacked [r][256]
#define SM_ATT   54272        // 160
#define SM_TOT_F 54432
#define SM_BYTES (SM_TOT_F*4)

// N=768 GEMM, 2-way k split over threads 0..383; pipelined float4 weight stream.
__device__ __forceinline__ void gemm768_ks2(const float* __restrict__ W,
                                            const float* __restrict__ bias,
                                            const float* sXp, float* sOut, int tid) {
    const int active = (tid < 384);
    const int half = (tid >= 192) ? 1 : 0;
    const int c0 = (active ? (half ? tid - 192 : tid) : 0) * 4;
    const int kb = half * 128;
    ull a01[4] = {0,0,0,0}, a23[4] = {0,0,0,0};
    if (active) {
        float4 wA[8], wB[8];
        #pragma unroll
        for (int u=0;u<8;u++) wA[u] = *(const float4*)(W + (size_t)(kb+u)*G3 + c0);
        for (int it = 0; it < 8; ++it) {
            int kA = kb + it*16;
            #pragma unroll
            for (int u=0;u<8;u++) wB[u] = *(const float4*)(W + (size_t)(kA+8+u)*G3 + c0);
            #pragma unroll
            for (int u=0;u<8;u++) {
                ull x01 = *(const ull*)(sXp + (kA+u)*4);
                ull x23 = *(const ull*)(sXp + (kA+u)*4 + 2);
                ull p0 = pk2(wA[u].x,wA[u].x), p1 = pk2(wA[u].y,wA[u].y);
                ull p2 = pk2(wA[u].z,wA[u].z), p3 = pk2(wA[u].w,wA[u].w);
                FMA2(a01[0],x01,p0); FMA2(a23[0],x23,p0);
                FMA2(a01[1],x01,p1); FMA2(a23[1],x23,p1);
                FMA2(a01[2],x01,p2); FMA2(a23[2],x23,p2);
                FMA2(a01[3],x01,p3); FMA2(a23[3],x23,p3);
            }
            int kAn = (it < 7) ? kA + 16 : kb;
            #pragma unroll
            for (int u=0;u<8;u++) wA[u] = *(const float4*)(W + (size_t)(kAn+u)*G3 + c0);
            #pragma unroll
            for (int u=0;u<8;u++) {
                ull x01 = *(const ull*)(sXp + (kA+8+u)*4);
                ull x23 = *(const ull*)(sXp + (kA+8+u)*4 + 2);
                ull p0 = pk2(wB[u].x,wB[u].x), p1 = pk2(wB[u].y,wB[u].y);
                ull p2 = pk2(wB[u].z,wB[u].z), p3 = pk2(wB[u].w,wB[u].w);
                FMA2(a01[0],x01,p0); FMA2(a23[0],x23,p0);
                FMA2(a01[1],x01,p1); FMA2(a23[1],x23,p1);
                FMA2(a01[2],x01,p2); FMA2(a23[2],x23,p2);
                FMA2(a01[3],x01,p3); FMA2(a23[3],x23,p3);
            }
        }
    }
    if (active && half) {
        #pragma unroll
        for (int j=0;j<4;j++) {
            float2 p01 = up2(a01[j]), p23 = up2(a23[j]);
            sOut[0*G3+c0+j] = p01.x; sOut[1*G3+c0+j] = p01.y;
            sOut[2*G3+c0+j] = p23.x; sOut[3*G3+c0+j] = p23.y;
        }
    }
    __syncthreads();
    if (active && !half) {
        #pragma unroll
        for (int j=0;j<4;j++) {
            float bv = bias[c0+j];
            float2 p01 = up2(a01[j]), p23 = up2(a23[j]);
            sOut[0*G3+c0+j] = sOut[0*G3+c0+j] + p01.x + bv;
            sOut[1*G3+c0+j] = sOut[1*G3+c0+j] + p01.y + bv;
            sOut[2*G3+c0+j] = sOut[2*G3+c0+j] + p23.x + bv;
            sOut[3*G3+c0+j] = sOut[3*G3+c0+j] + p23.y + bv;
        }
    }
    __syncthreads();
}

__global__ __launch_bounds__(THR) void k_steps(
    const int* __restrict__ lhs, const float* __restrict__ ts0,
    const float* __restrict__ emb, const float* __restrict__ mem,
    const float* __restrict__ Wx, const float* __restrict__ bx,
    const float* __restrict__ Wh, const float* __restrict__ bh,
    const float* __restrict__ Wc, const float* __restrict__ bc,
    const float* __restrict__ bsym)
{
    extern __shared__ float sm[];
    float* sMem  = sm + SM_MEM;
    float* sGh   = sm + SM_GH;
    float* sGx   = sm + SM_GX;
    float* sTs0  = sm + SM_TS0;
    float* sTs   = sm + SM_TS;
    float* sXp   = sm + SM_XP;
    float* sCatP = sm + SM_CATP;
    float* sSoaP = sm + SM_SOAP;
    float* sH    = sm + SM_H;
    float* sAtt  = sm + SM_ATT;
    __shared__ int sPrev[RPB];
    __shared__ ull sArg[RPB];
    __shared__ int sAcnt[RPB];
    __shared__ int sAlist[RPB][ALMAX];
    __shared__ float sAv[RPB][ALMAX];

    const int tid = threadIdx.x;
    const int lane = tid & 31, warp = tid >> 5;
    const int b0 = blockIdx.x * RPB;

    // ---- prologue
    {
        const float4* m4 = (const float4*)(mem + (size_t)b0*SRCs*Dd);
        float4* s4 = (float4*)sMem;
        for (int i = tid; i < RPB*SRCs*Dd/4; i += THR) s4[i] = m4[i];
    }
    for (int i = tid; i < RPB*Dd; i += THR) {
        float v = ts0[b0*Dd + i];
        sTs0[i] = v; sTs[i] = v;
        sXp[(i & 255)*4 + (i >> 8)] = v;
    }
    if (tid < RPB) { sPrev[tid] = lhs[b0 + tid]; sArg[tid] = 0ull; }
    __syncthreads();

    // gh = ts0 @ Wh + bh (constant across steps)
    gemm768_ks2(Wh, bh, sXp, sGh, tid);

    // ---- 10 steps
    for (int t = 0; t < SEQs; t++) {
        // load allowed lists for this step + gather x = emb[prev] packed
        if (tid >= 256 && tid < 256 + RPB*ALMAX) {
            int q = tid - 256;
            sAlist[q/ALMAX][q%ALMAX] = d_alist[(size_t)(t*Bb + b0 + q/ALMAX)*ALMAX + q%ALMAX];
        }
        if (tid >= 384 && tid < 384 + RPB)
            sAcnt[tid-384] = d_acnt[t*Bb + b0 + tid - 384];
        if (tid < 256) {
            int r = tid >> 6, q = tid & 63;
            float4 v = *(const float4*)(emb + (size_t)sPrev[r]*Dd + q*4);
            sXp[(q*4+0)*4 + r] = v.x;
            sXp[(q*4+1)*4 + r] = v.y;
            sXp[(q*4+2)*4 + r] = v.z;
            sXp[(q*4+3)*4 + r] = v.w;
        }
        __syncthreads();

        // gx = x @ Wx + bx  (pipelined, 384 threads)
        gemm768_ks2(Wx, bx, sXp, sGx, tid);

        // GRU gates -> h
        {
            int j = tid & 255, rr = tid >> 8;
            #pragma unroll
            for (int q = 0; q < 2; q++) {
                int r = rr*2 + q;
                float xr = sGx[r*G3 + j], xz = sGx[r*G3 + 256 + j], xn = sGx[r*G3 + 512 + j];
                float hr = sGh[r*G3 + j], hz = sGh[r*G3 + 256 + j], hn = sGh[r*G3 + 512 + j];
                float rg = 1.f/(1.f + expf(-(xr+hr)));
                float z  = 1.f/(1.f + expf(-(xz+hz)));
                float n  = tanhf(xn + rg*hn);
                float h  = (1.f - z)*n + z*sTs0[r*Dd + j];
                sH[r*256 + j] = h;
                sCatP[(256 + j)*4 + r] = h;
            }
        }
        __syncthreads();

        // attention dots
        for (int d = warp; d < RPB*SRCs; d += 16) {
            int r = d / SRCs, s = d % SRCs;
            const float* hrow = sH + r*256;
            const float* mrow = sMem + (r*SRCs + s)*Dd;
            float sum = 0.f;
            #pragma unroll
            for (int k = 0; k < 8; k++) sum += hrow[lane + k*32]*mrow[lane + k*32];
            #pragma unroll
            for (int o=16;o;o>>=1) sum += __shfl_down_sync(0xffffffffu, sum, o);
            if (lane == 0) sAtt[r*SRCs + s] = sum;
        }
        __syncthreads();

        // softmax (warps 0..3)
        if (warp < RPB) {
            int r = warp;
            float v0 = sAtt[r*SRCs + lane];
            float v1 = (lane < 8) ? sAtt[r*SRCs + 32 + lane] : -1e30f;
            float m = fmaxf(v0, v1);
            #pragma unroll
            for (int o=16;o;o>>=1) m = fmaxf(m, __shfl_xor_sync(0xffffffffu, m, o));
            float e0 = expf(v0 - m);
            float e1 = (lane < 8) ? expf(v1 - m) : 0.f;
            float s = e0 + e1;
            #pragma unroll
            for (int o=16;o;o>>=1) s += __shfl_xor_sync(0xffffffffu, s, o);
            float inv = 1.f/s;
            sAtt[r*SRCs + lane] = e0*inv;
            if (lane < 8) sAtt[r*SRCs + 32 + lane] = e1*inv;
        }
        __syncthreads();

        // ctx packed (float4 over j)
        if (tid < 256) {
            int r = tid >> 6, jg = (tid & 63) * 4;
            float4 acc = make_float4(0.f, 0.f, 0.f, 0.f);
            #pragma unroll 8
            for (int s = 0; s < SRCs; s++) {
                float a = sAtt[r*SRCs + s];
                float4 m4 = *(const float4*)(sMem + (r*SRCs + s)*Dd + jg);
                acc.x += a*m4.x; acc.y += a*m4.y; acc.z += a*m4.z; acc.w += a*m4.w;
            }
            sCatP[(jg+0)*4 + r] = acc.x;
            sCatP[(jg+1)*4 + r] = acc.y;
            sCatP[(jg+2)*4 + r] = acc.z;
            sCatP[(jg+3)*4 + r] = acc.w;
        }
        __syncthreads();

        // soa = tanh(cat @ Wc + bc); 4-way k-split, float2 loads, pipelined
        {
            const int sp = tid >> 7;
            const int cg = tid & 127;
            const int c0 = cg*2;
            const int kb = sp*128;
            ull a01[2] = {0,0}, a23[2] = {0,0};
            {
                float2 wA[8], wB[8];
                #pragma unroll
                for (int u=0;u<8;u++) wA[u] = *(const float2*)(Wc + (size_t)(kb+u)*Dd + c0);
                for (int it = 0; it < 8; ++it) {
                    int kA = kb + it*16;
                    #pragma unroll
                    for (int u=0;u<8;u++) wB[u] = *(const float2*)(Wc + (size_t)(kA+8+u)*Dd + c0);
                    #pragma unroll
                    for (int u=0;u<8;u++) {
                        ull x01 = *(const ull*)(sCatP + (kA+u)*4);
                        ull x23 = *(const ull*)(sCatP + (kA+u)*4 + 2);
                        ull p0 = pk2(wA[u].x,wA[u].x), p1 = pk2(wA[u].y,wA[u].y);
                        FMA2(a01[0],x01,p0); FMA2(a23[0],x23,p0);
                        FMA2(a01[1],x01,p1); FMA2(a23[1],x23,p1);
                    }
                    int kAn = (it < 7) ? kA + 16 : kb;
                    #pragma unroll
                    for (int u=0;u<8;u++) wA[u] = *(const float2*)(Wc + (size_t)(kAn+u)*Dd + c0);
                    #pragma unroll
                    for (int u=0;u<8;u++) {
                        ull x01 = *(const ull*)(sCatP + (kA+8+u)*4);
                        ull x23 = *(const ull*)(sCatP + (kA+8+u)*4 + 2);
                        ull p0 = pk2(wB[u].x,wB[u].x), p1 = pk2(wB[u].y,wB[u].y);
                        FMA2(a01[0],x01,p0); FMA2(a23[0],x23,p0);
                        FMA2(a01[1],x01,p1); FMA2(a23[1],x23,p1);
                    }
                }
            }
            if (sp > 0) {
                float* scr = sGx + (sp-1)*1024;
                #pragma unroll
                for (int j=0;j<2;j++) {
                    float2 p01 = up2(a01[j]), p23 = up2(a23[j]);
                    scr[(c0+j)*4+0] = p01.x; scr[(c0+j)*4+1] = p01.y;
                    scr[(c0+j)*4+2] = p23.x; scr[(c0+j)*4+3] = p23.y;
                }
            }
            __syncthreads();
            if (sp == 0) {
                #pragma unroll
                for (int j=0;j<2;j++) {
                    float2 p01 = up2(a01[j]), p23 = up2(a23[j]);
                    float v[4] = {p01.x, p01.y, p23.x, p23.y};
                    float bcv = bc[c0+j];
                    #pragma unroll
                    for (int r=0;r<4;r++) {
                        float sum = v[r] + sGx[0*1024+(c0+j)*4+r]
                                         + sGx[1*1024+(c0+j)*4+r]
                                         + sGx[2*1024+(c0+j)*4+r] + bcv;
                        float s = tanhf(sum);
                        sSoaP[(c0+j)*4+r] = s;
                        sTs[r*256+c0+j] = tanhf(sTs[r*256+c0+j] + s);
                    }
                }
            }
            __syncthreads();
        }

        // ---------- sparse masked logits: allowed columns only ----------
        {
            // warp-GEMV tasks over allowed columns (unconditional loads, padded lists)
            for (int task = warp; task < RPB*ALMAX; task += 16) {
                int r = task / ALMAX, i = task % ALMAX;
                int c = sAlist[r][i];
                const float* wc = d_WsymT + (size_t)c*Dd + lane*8;
                float4 wa = *(const float4*)wc;
                float4 wb = *(const float4*)(wc + 4);
                int k0 = lane*8;
                float s = wa.x*sSoaP[(k0+0)*4+r] + wa.y*sSoaP[(k0+1)*4+r]
                        + wa.z*sSoaP[(k0+2)*4+r] + wa.w*sSoaP[(k0+3)*4+r]
                        + wb.x*sSoaP[(k0+4)*4+r] + wb.y*sSoaP[(k0+5)*4+r]
                        + wb.z*sSoaP[(k0+6)*4+r] + wb.w*sSoaP[(k0+7)*4+r];
                #pragma unroll
                for (int o=16;o;o>>=1) s += __shfl_down_sync(0xffffffffu, s, o);
                if (lane == 0 && i < sAcnt[r]) {
                    float v = s + bsym[c];
                    sAv[r][i] = v;
                    ull key = ((ull)f2mono(v) << 32) | (0xFFFFFFFFu - (unsigned)c);
                    atomicMax(&sArg[r], key);
                }
            }
            // fallback: all-masked rows -> thread-per-column full argmax (rare)
            #pragma unroll
            for (int r = 0; r < RPB; r++) {
                if (sAcnt[r] == 0) {
                    ull bloc = 0ull;
                    for (int c = tid; c < Vv; c += THR) {
                        const float* wc = d_WsymT + (size_t)c*Dd;
                        float s = 0.f;
                        #pragma unroll 8
                        for (int k = 0; k < Dd; k += 4) {
                            float4 w = *(const float4*)(wc + k);
                            s += w.x*sSoaP[(k+0)*4+r] + w.y*sSoaP[(k+1)*4+r]
                               + w.z*sSoaP[(k+2)*4+r] + w.w*sSoaP[(k+3)*4+r];
                        }
                        float v = s + bsym[c];
                        ull key = ((ull)f2mono(v) << 32) | (0xFFFFFFFFu - (unsigned)c);
                        if (key > bloc) bloc = key;
                    }
                    #pragma unroll
                    for (int o=16;o;o>>=1) {
                        ull x = __shfl_xor_sync(0xffffffffu, bloc, o);
                        if (x > bloc) bloc = x;
                    }
                    if (lane == 0 && bloc) atomicMax(&sArg[r], bloc);
                }
            }
            __syncthreads();
            // lse over allowed set + store values (warps 0..3)
            if (warp < RPB) {
                int r = warp, cnt = sAcnt[r];
                if (cnt > 0) {
                    float v = (lane < cnt) ? sAv[r][lane] : -1e30f;
                    float m = v;
                    #pragma unroll
                    for (int o=16;o;o>>=1) m = fmaxf(m, __shfl_xor_sync(0xffffffffu, m, o));
                    float e = (lane < cnt) ? expf(v - m) : 0.f;
                    #pragma unroll
                    for (int o=16;o;o>>=1) e += __shfl_xor_sync(0xffffffffu, e, o);
                    if (lane == 0) d_lse[t*Bb + b0 + r] = m + logf(e);
                    if (lane < cnt) d_av[(size_t)(t*Bb + b0 + r)*ALMAX + lane] = v;
                }
            }
        }
        __syncthreads();
        if (tid < RPB) {
            sPrev[tid] = (int)(0xFFFFFFFFu - (unsigned)(sArg[tid] & 0xFFFFFFFFull));
            sArg[tid] = 0ull;
        }
        __syncthreads();
    }

    for (int i = tid; i < RPB*Dd; i += THR)
        d_ts[b0*Dd + i] = sTs[i];
}

// ============================================================================
// k_tail: per-batch opts + topo + prepA from compact allowed values. grid=256.
// ============================================================================
__global__ __launch_bounds__(256) void k_tail(const int* __restrict__ gg,
                                              const float* __restrict__ emb,
                                              float* __restrict__ out)
{
    const int b = blockIdx.x;
    const int tid = threadIdx.x;
    __shared__ int   sCnt[SEQs];
    __shared__ float sLse[SEQs];
    __shared__ int   sList[SEQs][ALMAX];
    __shared__ float sAvv[SEQs][ALMAX];
    __shared__ float sVals[OPTo*SEQs];
    __shared__ float sSol[OPTo];
    __shared__ int   sBest;
    __shared__ int   sSym[SEQs];

    if (tid < SEQs) {
        sCnt[tid] = d_acnt[tid*Bb + b];
        sLse[tid] = d_lse[tid*Bb + b];
    }
    if (tid < SEQs*ALMAX) {
        int t = tid / ALMAX, i = tid % ALMAX;
        sList[t][i] = d_alist[(size_t)(t*Bb + b)*ALMAX + i];
        sAvv[t][i]  = d_av[(size_t)(t*Bb + b)*ALMAX + i];
    }
    __syncthreads();
    if (tid < OPTo*SEQs) {
        int o = tid / SEQs, t = tid % SEQs;
        int base = ((b*OPTo + o)*4)*SEQs + t;
        int m = gg[base + 3*SEQs];
        float v = 0.f;
        if (m) {
            int sym = gg[base];
            float val = 0.f;
            int cnt = sCnt[t];
            for (int i = 0; i < cnt; i++) {
                if (sList[t][i] == sym) { val = sAvv[t][i]; break; }
            }
            v = logf(expf(val - sLse[t]) + 1e-13f);
        }
        sVals[tid] = v;
    }
    __syncthreads();
    if (tid < OPTo) {
        float s = 0.f;
        #pragma unroll
        for (int t=0;t<SEQs;t++) s += sVals[tid*SEQs + t];
        sSol[tid] = s;
        out[OFF_OPT + b*OPTo + tid] = s;
    }
    __syncthreads();
    if (tid == 0) {
        int bi = 0; float bv = sSol[0];
        for (int o=1;o<OPTo;o++) if (sSol[o] > bv) { bv = sSol[o]; bi = o; }
        sBest = bi;
    }
    __syncthreads();
    if (tid < 4*SEQs) {
        int c = tid / SEQs, s = tid % SEQs;
        int val = gg[((b*OPTo + sBest)*4 + c)*SEQs + s];
        out[OFF_TOPO + c*(Bb*SEQs) + b*SEQs + s] = (float)val;
        if (c == 0) { sSym[s] = val; d_sym[b*SEQs + s] = val; }
    }
    __syncthreads();
    for (int i = tid; i < SEQs*512; i += 256) {
        int s = i >> 9, k = i & 511;
        float v = (k < Dd) ? emb[(size_t)sSym[s]*Dd + k] : d_ts[b*Dd + (k - Dd)];
        d_Ahi[((size_t)b*SEQs + s)*512 + k] = __float2bfloat16(v);
    }
}

// ---------------- exact_logit GEMM: single bf16 mma, 128x128x32, double-buffered --
#define MMA16816(d, a, b) asm volatile( \
    "mma.sync.aligned.m16n8k16.row.col.f32.bf16.bf16.f32 " \
    "{%0,%1,%2,%3}, {%4,%5,%6,%7}, {%8,%9}, {%0,%1,%2,%3};\n" \
    : "+f"(d[0]), "+f"(d[1]), "+f"(d[2]), "+f"(d[3]) \
    : "r"(a[0]), "r"(a[1]), "r"(a[2]), "r"(a[3]), "r"(b[0]), "r"(b[1]))

#define XSTR 40

__global__ __launch_bounds__(256) void k_exact(const float* __restrict__ btok,
                                               const float* __restrict__ tok,
                                               float* __restrict__ out) {
    __shared__ __nv_bfloat16 sA[2][128*XSTR], sB[2][128*XSTR];
    int tid = threadIdx.x;
    int m0 = blockIdx.y*128, n0 = blockIdx.x*128;
    int lane = tid & 31, warp = tid >> 5;
    int wm = warp >> 2, wn = warp & 3;
    int g = lane >> 2, tq = lane & 3;
    float acc[4][4][4];
    #pragma unroll
    for (int i=0;i<4;i++) {
        #pragma unroll
        for (int j=0;j<4;j++) {
            #pragma unroll
            for (int q=0;q<4;q++) acc[i][j][q] = 0.f;
        }
    }

    int row = tid >> 1;
    int kh  = (tid & 1) << 4;
    int nr  = n0 + row;
    const bool nok = (nr < VTt);

    uint4 ra0, ra1, rb0, rb1;
    const uint4 z0 = make_uint4(0,0,0,0);

    {
        const uint4* p = (const uint4*)(d_Ahi + (size_t)(m0+row)*512 + kh);
        ra0 = p[0]; ra1 = p[1];
        rb0 = z0; rb1 = z0;
        if (nok) {
            const uint4* q = (const uint4*)(d_WhiT + (size_t)nr*512 + kh);
            rb0 = q[0]; rb1 = q[1];
        }
    }
    *(uint4*)&sA[0][row*XSTR + kh]     = ra0;
    *(uint4*)&sA[0][row*XSTR + kh + 8] = ra1;
    *(uint4*)&sB[0][row*XSTR + kh]     = rb0;
    *(uint4*)&sB[0][row*XSTR + kh + 8] = rb1;
    __syncthreads();

    int buf = 0;
    for (int k0 = 0; k0 < 512; k0 += 32) {
        int nxt = k0 + 32;
        if (nxt < 512) {
            const uint4* p = (const uint4*)(d_Ahi + (size_t)(m0+row)*512 + nxt + kh);
            ra0 = p[0]; ra1 = p[1];
            rb0 = z0; rb1 = z0;
            if (nok) {
                const uint4* q = (const uint4*)(d_WhiT + (size_t)nr*512 + nxt + kh);
                rb0 = q[0]; rb1 = q[1];
            }
        }
        const __nv_bfloat16* cA = sA[buf];
        const __nv_bfloat16* cB = sB[buf];
        #pragma unroll
        for (int ks = 0; ks < 2; ks++) {
            int kb = ks*16;
            uint32_t ah[4][4];
            #pragma unroll
            for (int mi=0;mi<4;mi++) {
                int rb = wm*64 + mi*16;
                int c0 = kb + tq*2;
                ah[mi][0] = *(const uint32_t*)&cA[(rb+g)*XSTR + c0];
                ah[mi][1] = *(const uint32_t*)&cA[(rb+g+8)*XSTR + c0];
                ah[mi][2] = *(const uint32_t*)&cA[(rb+g)*XSTR + c0 + 8];
                ah[mi][3] = *(const uint32_t*)&cA[(rb+g+8)*XSTR + c0 + 8];
            }
            uint32_t bh[4][2];
            #pragma unroll
            for (int ni=0;ni<4;ni++) {
                int nb = wn*32 + ni*8 + g;
                bh[ni][0] = *(const uint32_t*)&cB[nb*XSTR + kb + tq*2];
                bh[ni][1] = *(const uint32_t*)&cB[nb*XSTR + kb + tq*2 + 8];
            }
            #pragma unroll
            for (int mi=0;mi<4;mi++) {
                #pragma unroll
                for (int ni=0;ni<4;ni++) {
                    MMA16816(acc[mi][ni], ah[mi], bh[ni]);
                }
            }
        }
        if (nxt < 512) {
            *(uint4*)&sA[buf^1][row*XSTR + kh]     = ra0;
            *(uint4*)&sA[buf^1][row*XSTR + kh + 8] = ra1;
            *(uint4*)&sB[buf^1][row*XSTR + kh]     = rb0;
            *(uint4*)&sB[buf^1][row*XSTR + kh + 8] = rb1;
            __syncthreads();
            buf ^= 1;
        }
    }

    const float LT = logf(1e-13f);
    #pragma unroll
    for (int mi=0;mi<4;mi++) {
        int r0 = m0 + wm*64 + mi*16 + g;
        int s0 = d_sym[r0];
        int s1 = d_sym[r0 + 8];
        #pragma unroll
        for (int ni=0;ni<4;ni++) {
            int c0 = n0 + wn*32 + ni*8 + tq*2;
            if (c0 < VTt) {
                float b0 = btok[c0];
                out[OFF_EX + (size_t)r0*VTt + c0]     = acc[mi][ni][0] + b0 + (tok[(size_t)s0*VTt + c0] > 0.f ? 0.f : LT);
                out[OFF_EX + (size_t)(r0+8)*VTt + c0] = acc[mi][ni][2] + b0 + (tok[(size_t)s1*VTt + c0] > 0.f ? 0.f : LT);
            }
            if (c0 + 1 < VTt) {
                float b1 = btok[c0+1];
                out[OFF_EX + (size_t)r0*VTt + c0+1]     = acc[mi][ni][1] + b1 + (tok[(size_t)s0*VTt + c0+1] > 0.f ? 0.f : LT);
                out[OFF_EX + (size_t)(r0+8)*VTt + c0+1] = acc[mi][ni][3] + b1 + (tok[(size_t)s1*VTt + c0+1] > 0.f ? 0.f : LT);
            }
        }
    }
}

// ---------------- host launcher ----------------
extern "C" void kernel_launch(void* const* d_in, const int* in_sizes, int n_in,
                              void* d_out, int out_size) {
    const int*   lhs   = (const int*)d_in[0];
    const int*   lmask = (const int*)d_in[1];
    const float* ts0   = (const float*)d_in[2];
    const int*   gg    = (const int*)d_in[3];
    const float* emb   = (const float*)d_in[4];
    const float* mem   = (const float*)d_in[5];
    const float* Wx    = (const float*)d_in[6];
    const float* Wh    = (const float*)d_in[7];
    const float* bx    = (const float*)d_in[8];
    const float* bh    = (const float*)d_in[9];
    const float* Wc    = (const float*)d_in[10];
    const float* bc    = (const float*)d_in[11];
    const float* Wsym  = (const float*)d_in[12];
    const float* bsym  = (const float*)d_in[13];
    const float* Wtok  = (const float*)d_in[14];
    const float* btok  = (const float*)d_in[15];
    const float* tok   = (const float*)d_in[16];
    float* out = (float*)d_out;

    static bool attr_set = false;
    if (!attr_set) {
        cudaFuncSetAttribute(k_steps, cudaFuncAttributeMaxDynamicSharedMemorySize, SM_BYTES);
        attr_set = true;
    }

    k_alist<<<SEQs*Bb, 32>>>(gg);
    k_prepWT<<<dim3(63, 8), dim3(32, 8)>>>(Wsym);
    k_prepW<<<5008, 256>>>(Wtok);
    k_steps<<<GSTEP, THR, SM_BYTES>>>(lhs, ts0, emb, mem, Wx, bx, Wh, bh, Wc, bc, bsym);
    k_copy<<<642, 256>>>(lhs, lmask, gg, out);
    k_tail<<<Bb, 256>>>(gg, emb, out);
    k_exact<<<dim3((VTt+127)/128, (Bb*SEQs)/128), 256>>>(btok, tok, out);
}

// round 15
// speedup vs baseline: 1.4360x; 1.4360x over previous
#include <cuda_runtime.h>
#include <cuda_bf16.h>
#include <cstdint>

#define Bb   256
#define Dd   256
#define Vv   2000
#define VTt  10000
#define OPTo 16
#define SEQs 10
#define SRCs 40
#define G3   768
#define GSTEP 64
#define RPB   4
#define THR   512

#define OFF_OPT  164352
#define OFF_TOPO 168448
#define OFF_EX   178688

typedef unsigned long long ull;

// ---------------- device scratch ----------------
__device__ float d_ts[Bb*Dd];
__device__ float d_clog[SEQs*Bb*Vv];
__device__ unsigned char d_w[SEQs*Bb*Vv];
__device__ int   d_sym[Bb*SEQs];
__device__ __nv_bfloat16 d_Ahi[Bb*SEQs*2*Dd];
__device__ __nv_bfloat16 d_WhiT[(size_t)VTt*2*Dd];

__device__ __forceinline__ unsigned f2mono(float f) {
    unsigned u = __float_as_uint(f);
    return (u & 0x80000000u) ? ~u : (u | 0x80000000u);
}

// packed f32x2 helpers (sm_103a)
#define FMA2(d, a, b) asm("fma.rn.f32x2 %0, %1, %2, %0;" : "+l"(d) : "l"(a), "l"(b))
__device__ __forceinline__ ull pk2(float x, float y) {
    ull r;
    asm("mov.b64 %0, {%1,%2};" : "=l"(r) : "f"(x), "f"(y));
    return r;
}
__device__ __forceinline__ float2 up2(ull v) {
    float2 r;
    asm("mov.b64 {%0,%1}, %2;" : "=f"(r.x), "=f"(r.y) : "l"(v));
    return r;
}

// ---------------- grammar w masks ----------------
__global__ void k_w(const int* __restrict__ gg) {
    int tb = blockIdx.x;
    int t = tb / Bb, b = tb % Bb;
    int tid = threadIdx.x;
    __shared__ unsigned char ws[Vv];
    __shared__ int f0;
    for (int v = tid; v < Vv; v += 64) ws[v] = 0;
    if (tid == 0) f0 = 0;
    __syncthreads();
    if (tid < OPTo) {
        int base = ((b*OPTo + tid)*4)*SEQs + t;
        int sym = gg[base];
        int m   = gg[base + 3*SEQs];
        if (m) { if (sym > 0) ws[sym] = 1; else f0 = 1; }
    }
    __syncthreads();
    if (tid == 0) ws[0] = (unsigned char)f0;
    __syncthreads();
    unsigned char* outp = d_w + (size_t)tb*Vv;
    for (int v = tid; v < Vv; v += 64) outp[v] = ws[v];
}

// ---------------- copy small outputs ----------------
__global__ void k_copy(const int* __restrict__ lhs, const int* __restrict__ lmask,
                       const int* __restrict__ gg, float* __restrict__ out) {
    for (int i = blockIdx.x*blockDim.x + threadIdx.x; i < OFF_OPT; i += gridDim.x*blockDim.x) {
        if (i < 256)       out[i] = (float)lhs[i];
        else if (i < 512)  out[i] = (float)lmask[i-256];
        else               out[i] = (float)gg[i-512];
    }
}

// ---------------- prep W: Wtok transpose to (VT,512) bf16 ----------------
__global__ void k_prepW(const float* __restrict__ Wtok) {
    __shared__ float tile[32][33];
    int bi = blockIdx.x;
    int tid = threadIdx.x;
    int tx = tid & 31, ty = tid >> 5;
    int n0 = (bi % 313)*32, k0 = (bi / 313)*32;
    #pragma unroll
    for (int i=0;i<4;i++) {
        int k = k0 + ty + i*8, n = n0 + tx;
        tile[ty+i*8][tx] = (n < VTt) ? Wtok[(size_t)k*VTt + n] : 0.f;
    }
    __syncthreads();
    #pragma unroll
    for (int i=0;i<4;i++) {
        int n = n0 + ty + i*8, k = k0 + tx;
        if (n < VTt)
            d_WhiT[(size_t)n*512 + k] = __float2bfloat16(tile[tx][ty+i*8]);
    }
}

// ============================================================================
// k_steps: 64 blocks x 4 batches, 512 threads, pipelined f32x2 streaming GEMMs.
// ============================================================================
#define SM_MEM   0            // 40960
#define SM_GH    40960        // 3072
#define SM_GX    44032        // 3072   (also soa-phase scratch: dead then)
#define SM_TS0   47104        // 1024
#define SM_TS    48128        // 1024
#define SM_XP    49152        // 1024  packed [k][4]
#define SM_CATP  50176        // 2048  packed [k][4]
#define SM_SOAP  52224        // 1024  packed [k][4]
#define SM_H     53248        // 1024  unpacked [r][256]
#define SM_ATT   54272        // 160
#define SM_TOT_F 54432
#define SM_BYTES (SM_TOT_F*4)

// N=768 GEMM, 2-way k split over threads 0..383; pipelined float4 weight stream.
// Contains __syncthreads — call from ALL threads.
__device__ __forceinline__ void gemm768_ks2(const float* __restrict__ W,
                                            const float* __restrict__ bias,
                                            const float* sXp, float* sOut, int tid) {
    const int active = (tid < 384);
    const int half = (tid >= 192) ? 1 : 0;
    const int c0 = (active ? (half ? tid - 192 : tid) : 0) * 4;
    const int kb = half * 128;
    ull a01[4] = {0,0,0,0}, a23[4] = {0,0,0,0};
    if (active) {
        float4 wA[8], wB[8];
        #pragma unroll
        for (int u=0;u<8;u++) wA[u] = *(const float4*)(W + (size_t)(kb+u)*G3 + c0);
        for (int it = 0; it < 8; ++it) {
            int kA = kb + it*16;
            #pragma unroll
            for (int u=0;u<8;u++) wB[u] = *(const float4*)(W + (size_t)(kA+8+u)*G3 + c0);
            #pragma unroll
            for (int u=0;u<8;u++) {
                ull x01 = *(const ull*)(sXp + (kA+u)*4);
                ull x23 = *(const ull*)(sXp + (kA+u)*4 + 2);
                ull p0 = pk2(wA[u].x,wA[u].x), p1 = pk2(wA[u].y,wA[u].y);
                ull p2 = pk2(wA[u].z,wA[u].z), p3 = pk2(wA[u].w,wA[u].w);
                FMA2(a01[0],x01,p0); FMA2(a23[0],x23,p0);
                FMA2(a01[1],x01,p1); FMA2(a23[1],x23,p1);
                FMA2(a01[2],x01,p2); FMA2(a23[2],x23,p2);
                FMA2(a01[3],x01,p3); FMA2(a23[3],x23,p3);
            }
            int kAn = (it < 7) ? kA + 16 : kb;
            #pragma unroll
            for (int u=0;u<8;u++) wA[u] = *(const float4*)(W + (size_t)(kAn+u)*G3 + c0);
            #pragma unroll
            for (int u=0;u<8;u++) {
                ull x01 = *(const ull*)(sXp + (kA+8+u)*4);
                ull x23 = *(const ull*)(sXp + (kA+8+u)*4 + 2);
                ull p0 = pk2(wB[u].x,wB[u].x), p1 = pk2(wB[u].y,wB[u].y);
                ull p2 = pk2(wB[u].z,wB[u].z), p3 = pk2(wB[u].w,wB[u].w);
                FMA2(a01[0],x01,p0); FMA2(a23[0],x23,p0);
                FMA2(a01[1],x01,p1); FMA2(a23[1],x23,p1);
                FMA2(a01[2],x01,p2); FMA2(a23[2],x23,p2);
                FMA2(a01[3],x01,p3); FMA2(a23[3],x23,p3);
            }
        }
    }
    if (active && half) {
        #pragma unroll
        for (int j=0;j<4;j++) {
            float2 p01 = up2(a01[j]), p23 = up2(a23[j]);
            sOut[0*G3+c0+j] = p01.x; sOut[1*G3+c0+j] = p01.y;
            sOut[2*G3+c0+j] = p23.x; sOut[3*G3+c0+j] = p23.y;
        }
    }
    __syncthreads();
    if (active && !half) {
        #pragma unroll
        for (int j=0;j<4;j++) {
            float bv = bias[c0+j];
            float2 p01 = up2(a01[j]), p23 = up2(a23[j]);
            sOut[0*G3+c0+j] = sOut[0*G3+c0+j] + p01.x + bv;
            sOut[1*G3+c0+j] = sOut[1*G3+c0+j] + p01.y + bv;
            sOut[2*G3+c0+j] = sOut[2*G3+c0+j] + p23.x + bv;
            sOut[3*G3+c0+j] = sOut[3*G3+c0+j] + p23.y + bv;
        }
    }
    __syncthreads();
}

__global__ __launch_bounds__(THR) void k_steps(
    const int* __restrict__ lhs, const float* __restrict__ ts0,
    const float* __restrict__ emb, const float* __restrict__ mem,
    const float* __restrict__ Wx, const float* __restrict__ bx,
    const float* __restrict__ Wh, const float* __restrict__ bh,
    const float* __restrict__ Wc, const float* __restrict__ bc,
    const float* __restrict__ Wsym, const float* __restrict__ bsym)
{
    extern __shared__ float sm[];
    float* sMem  = sm + SM_MEM;
    float* sGh   = sm + SM_GH;
    float* sGx   = sm + SM_GX;
    float* sTs0  = sm + SM_TS0;
    float* sTs   = sm + SM_TS;
    float* sXp   = sm + SM_XP;
    float* sCatP = sm + SM_CATP;
    float* sSoaP = sm + SM_SOAP;
    float* sH    = sm + SM_H;
    float* sAtt  = sm + SM_ATT;
    __shared__ int sPrev[RPB];
    __shared__ unsigned long long sArg[RPB];

    const int tid = threadIdx.x;
    const int lane = tid & 31, warp = tid >> 5;
    const int b0 = blockIdx.x * RPB;
    const float LT = logf(1e-13f);

    // ---- prologue
    {
        const float4* m4 = (const float4*)(mem + (size_t)b0*SRCs*Dd);
        float4* s4 = (float4*)sMem;
        for (int i = tid; i < RPB*SRCs*Dd/4; i += THR) s4[i] = m4[i];
    }
    for (int i = tid; i < RPB*Dd; i += THR) {
        float v = ts0[b0*Dd + i];
        sTs0[i] = v; sTs[i] = v;
        sXp[(i & 255)*4 + (i >> 8)] = v;
    }
    if (tid < RPB) { sPrev[tid] = lhs[b0 + tid]; sArg[tid] = 0ull; }
    __syncthreads();

    // gh = ts0 @ Wh + bh (constant across steps)
    gemm768_ks2(Wh, bh, sXp, sGh, tid);

    // ---- 10 steps
    for (int t = 0; t < SEQs; t++) {
        // gather x = emb[prev] packed
        if (tid < 256) {
            int r = tid >> 6, q = tid & 63;
            float4 v = *(const float4*)(emb + (size_t)sPrev[r]*Dd + q*4);
            sXp[(q*4+0)*4 + r] = v.x;
            sXp[(q*4+1)*4 + r] = v.y;
            sXp[(q*4+2)*4 + r] = v.z;
            sXp[(q*4+3)*4 + r] = v.w;
        }
        __syncthreads();

        // gx = x @ Wx + bx  (pipelined, 384 threads)
        gemm768_ks2(Wx, bx, sXp, sGx, tid);

        // GRU gates -> h
        {
            int j = tid & 255, rr = tid >> 8;
            #pragma unroll
            for (int q = 0; q < 2; q++) {
                int r = rr*2 + q;
                float xr = sGx[r*G3 + j], xz = sGx[r*G3 + 256 + j], xn = sGx[r*G3 + 512 + j];
                float hr = sGh[r*G3 + j], hz = sGh[r*G3 + 256 + j], hn = sGh[r*G3 + 512 + j];
                float rg = 1.f/(1.f + expf(-(xr+hr)));
                float z  = 1.f/(1.f + expf(-(xz+hz)));
                float n  = tanhf(xn + rg*hn);
                float h  = (1.f - z)*n + z*sTs0[r*Dd + j];
                sH[r*256 + j] = h;
                sCatP[(256 + j)*4 + r] = h;
            }
        }
        __syncthreads();

        // attention dots
        for (int d = warp; d < RPB*SRCs; d += 16) {
            int r = d / SRCs, s = d % SRCs;
            const float* hrow = sH + r*256;
            const float* mrow = sMem + (r*SRCs + s)*Dd;
            float sum = 0.f;
            #pragma unroll
            for (int k = 0; k < 8; k++) sum += hrow[lane + k*32]*mrow[lane + k*32];
            #pragma unroll
            for (int o=16;o;o>>=1) sum += __shfl_down_sync(0xffffffffu, sum, o);
            if (lane == 0) sAtt[r*SRCs + s] = sum;
        }
        __syncthreads();

        // softmax (warps 0..3)
        if (warp < RPB) {
            int r = warp;
            float v0 = sAtt[r*SRCs + lane];
            float v1 = (lane < 8) ? sAtt[r*SRCs + 32 + lane] : -1e30f;
            float m = fmaxf(v0, v1);
            #pragma unroll
            for (int o=16;o;o>>=1) m = fmaxf(m, __shfl_xor_sync(0xffffffffu, m, o));
            float e0 = expf(v0 - m);
            float e1 = (lane < 8) ? expf(v1 - m) : 0.f;
            float s = e0 + e1;
            #pragma unroll
            for (int o=16;o;o>>=1) s += __shfl_xor_sync(0xffffffffu, s, o);
            float inv = 1.f/s;
            sAtt[r*SRCs + lane] = e0*inv;
            if (lane < 8) sAtt[r*SRCs + 32 + lane] = e1*inv;
        }
        __syncthreads();

        // ctx packed
        {
            int j = tid & 255, rr = tid >> 8;
            #pragma unroll
            for (int q = 0; q < 2; q++) {
                int r = rr*2 + q;
                float cx = 0.f;
                #pragma unroll 8
                for (int s=0;s<SRCs;s++) cx += sAtt[r*SRCs + s]*sMem[(r*SRCs + s)*Dd + j];
                sCatP[j*4 + r] = cx;
            }
        }
        __syncthreads();

        // soa = tanh(cat @ Wc + bc); 4-way k-split, float2 loads, pipelined
        {
            const int sp = tid >> 7;
            const int cg = tid & 127;
            const int c0 = cg*2;
            const int kb = sp*128;
            ull a01[2] = {0,0}, a23[2] = {0,0};
            {
                float2 wA[8], wB[8];
                #pragma unroll
                for (int u=0;u<8;u++) wA[u] = *(const float2*)(Wc + (size_t)(kb+u)*Dd + c0);
                for (int it = 0; it < 8; ++it) {
                    int kA = kb + it*16;
                    #pragma unroll
                    for (int u=0;u<8;u++) wB[u] = *(const float2*)(Wc + (size_t)(kA+8+u)*Dd + c0);
                    #pragma unroll
                    for (int u=0;u<8;u++) {
                        ull x01 = *(const ull*)(sCatP + (kA+u)*4);
                        ull x23 = *(const ull*)(sCatP + (kA+u)*4 + 2);
                        ull p0 = pk2(wA[u].x,wA[u].x), p1 = pk2(wA[u].y,wA[u].y);
                        FMA2(a01[0],x01,p0); FMA2(a23[0],x23,p0);
                        FMA2(a01[1],x01,p1); FMA2(a23[1],x23,p1);
                    }
                    int kAn = (it < 7) ? kA + 16 : kb;
                    #pragma unroll
                    for (int u=0;u<8;u++) wA[u] = *(const float2*)(Wc + (size_t)(kAn+u)*Dd + c0);
                    #pragma unroll
                    for (int u=0;u<8;u++) {
                        ull x01 = *(const ull*)(sCatP + (kA+8+u)*4);
                        ull x23 = *(const ull*)(sCatP + (kA+8+u)*4 + 2);
                        ull p0 = pk2(wB[u].x,wB[u].x), p1 = pk2(wB[u].y,wB[u].y);
                        FMA2(a01[0],x01,p0); FMA2(a23[0],x23,p0);
                        FMA2(a01[1],x01,p1); FMA2(a23[1],x23,p1);
                    }
                }
            }
            if (sp > 0) {
                float* scr = sGx + (sp-1)*1024;
                #pragma unroll
                for (int j=0;j<2;j++) {
                    float2 p01 = up2(a01[j]), p23 = up2(a23[j]);
                    scr[(c0+j)*4+0] = p01.x; scr[(c0+j)*4+1] = p01.y;
                    scr[(c0+j)*4+2] = p23.x; scr[(c0+j)*4+3] = p23.y;
                }
            }
            __syncthreads();
            if (sp == 0) {
                #pragma unroll
                for (int j=0;j<2;j++) {
                    float2 p01 = up2(a01[j]), p23 = up2(a23[j]);
                    float v[4] = {p01.x, p01.y, p23.x, p23.y};
                    float bcv = bc[c0+j];
                    #pragma unroll
                    for (int r=0;r<4;r++) {
                        float sum = v[r] + sGx[0*1024+(c0+j)*4+r]
                                         + sGx[1*1024+(c0+j)*4+r]
                                         + sGx[2*1024+(c0+j)*4+r] + bcv;
                        float s = tanhf(sum);
                        sSoaP[(c0+j)*4+r] = s;
                        sTs[r*256+c0+j] = tanhf(sTs[r*256+c0+j] + s);
                    }
                }
            }
            __syncthreads();
        }

        // logits = soa @ Wsym + bsym + mask; pipelined; argmax
        {
            unsigned long long best[RPB] = {0ull,0ull,0ull,0ull};
            if (tid < 500) {
                int c0 = tid*4;
                ull a01[4] = {0,0,0,0}, a23[4] = {0,0,0,0};
                float4 wA[8], wB[8];
                #pragma unroll
                for (int u=0;u<8;u++) wA[u] = *(const float4*)(Wsym + (size_t)u*Vv + c0);
                for (int it = 0; it < 16; ++it) {
                    int kA = it*16;
                    #pragma unroll
                    for (int u=0;u<8;u++) wB[u] = *(const float4*)(Wsym + (size_t)(kA+8+u)*Vv + c0);
                    #pragma unroll
                    for (int u=0;u<8;u++) {
                        ull x01 = *(const ull*)(sSoaP + (kA+u)*4);
                        ull x23 = *(const ull*)(sSoaP + (kA+u)*4 + 2);
                        ull p0 = pk2(wA[u].x,wA[u].x), p1 = pk2(wA[u].y,wA[u].y);
                        ull p2 = pk2(wA[u].z,wA[u].z), p3 = pk2(wA[u].w,wA[u].w);
                        FMA2(a01[0],x01,p0); FMA2(a23[0],x23,p0);
                        FMA2(a01[1],x01,p1); FMA2(a23[1],x23,p1);
                        FMA2(a01[2],x01,p2); FMA2(a23[2],x23,p2);
                        FMA2(a01[3],x01,p3); FMA2(a23[3],x23,p3);
                    }
                    int kAn = (it < 15) ? kA + 16 : 0;
                    #pragma unroll
                    for (int u=0;u<8;u++) wA[u] = *(const float4*)(Wsym + (size_t)(kAn+u)*Vv + c0);
                    #pragma unroll
                    for (int u=0;u<8;u++) {
                        ull x01 = *(const ull*)(sSoaP + (kA+8+u)*4);
                        ull x23 = *(const ull*)(sSoaP + (kA+8+u)*4 + 2);
                        ull p0 = pk2(wB[u].x,wB[u].x), p1 = pk2(wB[u].y,wB[u].y);
                        ull p2 = pk2(wB[u].z,wB[u].z), p3 = pk2(wB[u].w,wB[u].w);
                        FMA2(a01[0],x01,p0); FMA2(a23[0],x23,p0);
                        FMA2(a01[1],x01,p1); FMA2(a23[1],x23,p1);
                        FMA2(a01[2],x01,p2); FMA2(a23[2],x23,p2);
                        FMA2(a01[3],x01,p3); FMA2(a23[3],x23,p3);
                    }
                }
                float4 bs = *(const float4*)(bsym + c0);
                float vb[4] = {bs.x, bs.y, bs.z, bs.w};
                float vr[RPB][4];
                #pragma unroll
                for (int j=0;j<4;j++) {
                    float2 p01 = up2(a01[j]), p23 = up2(a23[j]);
                    vr[0][j] = p01.x + vb[j];
                    vr[1][j] = p01.y + vb[j];
                    vr[2][j] = p23.x + vb[j];
                    vr[3][j] = p23.y + vb[j];
                }
                #pragma unroll
                for (int r=0;r<RPB;r++) {
                    int row = t*Bb + b0 + r;
                    uchar4 wm = *(const uchar4*)(d_w + (size_t)row*Vv + c0);
                    unsigned char wmv[4] = {wm.x, wm.y, wm.z, wm.w};
                    float4 st;
                    float* stp = &st.x;
                    #pragma unroll
                    for (int j=0;j<4;j++) {
                        float v = vr[r][j];
                        if (!wmv[j]) v += LT;
                        stp[j] = v;
                        unsigned long long key = ((unsigned long long)f2mono(v) << 32)
                                               | (0xFFFFFFFFu - (unsigned)(c0 + j));
                        if (key > best[r]) best[r] = key;
                    }
                    *(float4*)(d_clog + (size_t)row*Vv + c0) = st;
                }
            }
            #pragma unroll
            for (int r=0;r<RPB;r++) {
                unsigned long long bv = best[r];
                #pragma unroll
                for (int o=16;o;o>>=1) {
                    unsigned long long x = __shfl_xor_sync(0xffffffffu, bv, o);
                    if (x > bv) bv = x;
                }
                if (lane == 0 && bv) atomicMax(&sArg[r], bv);
            }
        }
        __syncthreads();
        if (tid < RPB) {
            sPrev[tid] = (int)(0xFFFFFFFFu - (unsigned)(sArg[tid] & 0xFFFFFFFFull));
            sArg[tid] = 0ull;
        }
        __syncthreads();
    }

    for (int i = tid; i < RPB*Dd; i += THR)
        d_ts[b0*Dd + i] = sTs[i];
}

// ============================================================================
// k_tail: per-batch lse + opts + topo + prepA. grid=256.
// ============================================================================
__global__ __launch_bounds__(256) void k_tail(const int* __restrict__ gg,
                                              const float* __restrict__ emb,
                                              float* __restrict__ out)
{
    const int b = blockIdx.x;
    const int tid = threadIdx.x;
    const int lane = tid & 31, warp = tid >> 5;
    __shared__ float sLse[SEQs];
    __shared__ float sVals[OPTo*SEQs];
    __shared__ float sSol[OPTo];
    __shared__ int   sBest;
    __shared__ int   sSym[SEQs];

    for (int t = warp; t < SEQs; t += 8) {
        const float* row = d_clog + ((size_t)t*Bb + b)*Vv;
        float m = -1e30f;
        for (int v = lane; v < Vv; v += 32) m = fmaxf(m, row[v]);
        #pragma unroll
        for (int o=16;o;o>>=1) m = fmaxf(m, __shfl_xor_sync(0xffffffffu, m, o));
        float s = 0.f;
        for (int v = lane; v < Vv; v += 32) s += expf(row[v]-m);
        #pragma unroll
        for (int o=16;o;o>>=1) s += __shfl_xor_sync(0xffffffffu, s, o);
        if (lane == 0) sLse[t] = m + logf(s);
    }
    __syncthreads();
    if (tid < OPTo*SEQs) {
        int o = tid / SEQs, t = tid % SEQs;
        int base = ((b*OPTo + o)*4)*SEQs + t;
        int m = gg[base + 3*SEQs];
        float v = 0.f;
        if (m) {
            int sym = gg[base];
            v = logf(expf(d_clog[((size_t)t*Bb + b)*Vv + sym] - sLse[t]) + 1e-13f);
        }
        sVals[tid] = v;
    }
    __syncthreads();
    if (tid < OPTo) {
        float s = 0.f;
        #pragma unroll
        for (int t=0;t<SEQs;t++) s += sVals[tid*SEQs + t];
        sSol[tid] = s;
        out[OFF_OPT + b*OPTo + tid] = s;
    }
    __syncthreads();
    if (tid == 0) {
        int bi = 0; float bv = sSol[0];
        for (int o=1;o<OPTo;o++) if (sSol[o] > bv) { bv = sSol[o]; bi = o; }
        sBest = bi;
    }
    __syncthreads();
    if (tid < 4*SEQs) {
        int c = tid / SEQs, s = tid % SEQs;
        int val = gg[((b*OPTo + sBest)*4 + c)*SEQs + s];
        out[OFF_TOPO + c*(Bb*SEQs) + b*SEQs + s] = (float)val;
        if (c == 0) { sSym[s] = val; d_sym[b*SEQs + s] = val; }
    }
    __syncthreads();
    for (int i = tid; i < SEQs*512; i += 256) {
        int s = i >> 9, k = i & 511;
        float v = (k < Dd) ? emb[(size_t)sSym[s]*Dd + k] : d_ts[b*Dd + (k - Dd)];
        d_Ahi[((size_t)b*SEQs + s)*512 + k] = __float2bfloat16(v);
    }
}

// ---------------- exact_logit GEMM: single bf16 mma, 128x128x32, double-buffered --
#define MMA16816(d, a, b) asm volatile( \
    "mma.sync.aligned.m16n8k16.row.col.f32.bf16.bf16.f32 " \
    "{%0,%1,%2,%3}, {%4,%5,%6,%7}, {%8,%9}, {%0,%1,%2,%3};\n" \
    : "+f"(d[0]), "+f"(d[1]), "+f"(d[2]), "+f"(d[3]) \
    : "r"(a[0]), "r"(a[1]), "r"(a[2]), "r"(a[3]), "r"(b[0]), "r"(b[1]))

#define XSTR 40

__global__ __launch_bounds__(256) void k_exact(const float* __restrict__ btok,
                                               const float* __restrict__ tok,
                                               float* __restrict__ out) {
    __shared__ __nv_bfloat16 sA[2][128*XSTR], sB[2][128*XSTR];
    int tid = threadIdx.x;
    int m0 = blockIdx.y*128, n0 = blockIdx.x*128;
    int lane = tid & 31, warp = tid >> 5;
    int wm = warp >> 2, wn = warp & 3;
    int g = lane >> 2, tq = lane & 3;
    float acc[4][4][4];
    #pragma unroll
    for (int i=0;i<4;i++) {
        #pragma unroll
        for (int j=0;j<4;j++) {
            #pragma unroll
            for (int q=0;q<4;q++) acc[i][j][q] = 0.f;
        }
    }

    int row = tid >> 1;
    int kh  = (tid & 1) << 4;
    int nr  = n0 + row;
    const bool nok = (nr < VTt);

    uint4 ra0, ra1, rb0, rb1;
    const uint4 z0 = make_uint4(0,0,0,0);

    {
        const uint4* p = (const uint4*)(d_Ahi + (size_t)(m0+row)*512 + kh);
        ra0 = p[0]; ra1 = p[1];
        rb0 = z0; rb1 = z0;
        if (nok) {
            const uint4* q = (const uint4*)(d_WhiT + (size_t)nr*512 + kh);
            rb0 = q[0]; rb1 = q[1];
        }
    }
    *(uint4*)&sA[0][row*XSTR + kh]     = ra0;
    *(uint4*)&sA[0][row*XSTR + kh + 8] = ra1;
    *(uint4*)&sB[0][row*XSTR + kh]     = rb0;
    *(uint4*)&sB[0][row*XSTR + kh + 8] = rb1;
    __syncthreads();

    int buf = 0;
    for (int k0 = 0; k0 < 512; k0 += 32) {
        int nxt = k0 + 32;
        if (nxt < 512) {
            const uint4* p = (const uint4*)(d_Ahi + (size_t)(m0+row)*512 + nxt + kh);
            ra0 = p[0]; ra1 = p[1];
            rb0 = z0; rb1 = z0;
            if (nok) {
                const uint4* q = (const uint4*)(d_WhiT + (size_t)nr*512 + nxt + kh);
                rb0 = q[0]; rb1 = q[1];
            }
        }
        const __nv_bfloat16* cA = sA[buf];
        const __nv_bfloat16* cB = sB[buf];
        #pragma unroll
        for (int ks = 0; ks < 2; ks++) {
            int kb = ks*16;
            uint32_t ah[4][4];
            #pragma unroll
            for (int mi=0;mi<4;mi++) {
                int rb = wm*64 + mi*16;
                int c0 = kb + tq*2;
                ah[mi][0] = *(const uint32_t*)&cA[(rb+g)*XSTR + c0];
                ah[mi][1] = *(const uint32_t*)&cA[(rb+g+8)*XSTR + c0];
                ah[mi][2] = *(const uint32_t*)&cA[(rb+g)*XSTR + c0 + 8];
                ah[mi][3] = *(const uint32_t*)&cA[(rb+g+8)*XSTR + c0 + 8];
            }
            uint32_t bh[4][2];
            #pragma unroll
            for (int ni=0;ni<4;ni++) {
                int nb = wn*32 + ni*8 + g;
                bh[ni][0] = *(const uint32_t*)&cB[nb*XSTR + kb + tq*2];
                bh[ni][1] = *(const uint32_t*)&cB[nb*XSTR + kb + tq*2 + 8];
            }
            #pragma unroll
            for (int mi=0;mi<4;mi++) {
                #pragma unroll
                for (int ni=0;ni<4;ni++) {
                    MMA16816(acc[mi][ni], ah[mi], bh[ni]);
                }
            }
        }
        if (nxt < 512) {
            *(uint4*)&sA[buf^1][row*XSTR + kh]     = ra0;
            *(uint4*)&sA[buf^1][row*XSTR + kh + 8] = ra1;
            *(uint4*)&sB[buf^1][row*XSTR + kh]     = rb0;
            *(uint4*)&sB[buf^1][row*XSTR + kh + 8] = rb1;
            __syncthreads();
            buf ^= 1;
        }
    }

    const float LT = logf(1e-13f);
    #pragma unroll
    for (int mi=0;mi<4;mi++) {
        int r0 = m0 + wm*64 + mi*16 + g;
        int s0 = d_sym[r0];
        int s1 = d_sym[r0 + 8];
        #pragma unroll
        for (int ni=0;ni<4;ni++) {
            int c0 = n0 + wn*32 + ni*8 + tq*2;
            if (c0 < VTt) {
                float b0 = btok[c0];
                out[OFF_EX + (size_t)r0*VTt + c0]     = acc[mi][ni][0] + b0 + (tok[(size_t)s0*VTt + c0] > 0.f ? 0.f : LT);
                out[OFF_EX + (size_t)(r0+8)*VTt + c0] = acc[mi][ni][2] + b0 + (tok[(size_t)s1*VTt + c0] > 0.f ? 0.f : LT);
            }
            if (c0 + 1 < VTt) {
                float b1 = btok[c0+1];
                out[OFF_EX + (size_t)r0*VTt + c0+1]     = acc[mi][ni][1] + b1 + (tok[(size_t)s0*VTt + c0+1] > 0.f ? 0.f : LT);
                out[OFF_EX + (size_t)(r0+8)*VTt + c0+1] = acc[mi][ni][3] + b1 + (tok[(size_t)s1*VTt + c0+1] > 0.f ? 0.f : LT);
            }
        }
    }
}

// ---------------- host launcher ----------------
extern "C" void kernel_launch(void* const* d_in, const int* in_sizes, int n_in,
                              void* d_out, int out_size) {
    const int*   lhs   = (const int*)d_in[0];
    const int*   lmask = (const int*)d_in[1];
    const float* ts0   = (const float*)d_in[2];
    const int*   gg    = (const int*)d_in[3];
    const float* emb   = (const float*)d_in[4];
    const float* mem   = (const float*)d_in[5];
    const float* Wx    = (const float*)d_in[6];
    const float* Wh    = (const float*)d_in[7];
    const float* bx    = (const float*)d_in[8];
    const float* bh    = (const float*)d_in[9];
    const float* Wc    = (const float*)d_in[10];
    const float* bc    = (const float*)d_in[11];
    const float* Wsym  = (const float*)d_in[12];
    const float* bsym  = (const float*)d_in[13];
    const float* Wtok  = (const float*)d_in[14];
    const float* btok  = (const float*)d_in[15];
    const float* tok   = (const float*)d_in[16];
    float* out = (float*)d_out;

    static bool attr_set = false;
    if (!attr_set) {
        cudaFuncSetAttribute(k_steps, cudaFuncAttributeMaxDynamicSharedMemorySize, SM_BYTES);
        attr_set = true;
    }

    k_w<<<SEQs*Bb, 64>>>(gg);
    k_prepW<<<5008, 256>>>(Wtok);
    k_copy<<<642, 256>>>(lhs, lmask, gg, out);
    k_steps<<<GSTEP, THR, SM_BYTES>>>(lhs, ts0, emb, mem, Wx, bx, Wh, bh, Wc, bc, Wsym, bsym);
    k_tail<<<Bb, 256>>>(gg, emb, out);
    k_exact<<<dim3((VTt+127)/128, (Bb*SEQs)/128), 256>>>(btok, tok, out);
}

// round 16
// speedup vs baseline: 1.6184x; 1.1270x over previous
#include <cuda_runtime.h>
#include <cuda_bf16.h>
#include <cstdint>

#define Bb   256
#define Dd   256
#define Vv   2000
#define VTt  10000
#define OPTo 16
#define SEQs 10
#define SRCs 40
#define G3   768
#define GPAIRS 64
#define GSTEP 128
#define RPB   4
#define THR   512

#define OFF_OPT  164352
#define OFF_TOPO 168448
#define OFF_EX   178688

typedef unsigned long long ull;

// ---------------- device scratch ----------------
__device__ float d_ts[Bb*Dd];
__device__ float d_clog[SEQs*Bb*Vv];
__device__ unsigned char d_w[SEQs*Bb*Vv];
__device__ int   d_sym[Bb*SEQs];
__device__ float d_gxg[GPAIRS*RPB*G3];
__device__ ull   d_pairArg[GPAIRS*SEQs*RPB];
__device__ volatile unsigned d_psync[GPAIRS];
__device__ __nv_bfloat16 d_Ahi[Bb*SEQs*2*Dd];
__device__ __nv_bfloat16 d_WhiT[(size_t)VTt*2*Dd];

__device__ __forceinline__ unsigned f2mono(float f) {
    unsigned u = __float_as_uint(f);
    return (u & 0x80000000u) ? ~u : (u | 0x80000000u);
}

// packed f32x2 helpers (sm_103a)
#define FMA2(d, a, b) asm("fma.rn.f32x2 %0, %1, %2, %0;" : "+l"(d) : "l"(a), "l"(b))
__device__ __forceinline__ ull pk2(float x, float y) {
    ull r;
    asm("mov.b64 %0, {%1,%2};" : "=l"(r) : "f"(x), "f"(y));
    return r;
}
__device__ __forceinline__ float2 up2(ull v) {
    float2 r;
    asm("mov.b64 {%0,%1}, %2;" : "=f"(r.x), "=f"(r.y) : "l"(v));
    return r;
}

// pair barrier: both blocks of pair p call with identical gen sequence (1,2,3,...)
__device__ __forceinline__ void psync(int p, int gen) {
    __threadfence();
    __syncthreads();
    if (threadIdx.x == 0) {
        atomicAdd((unsigned*)&d_psync[p], 1u);
        unsigned tgt = 2u*(unsigned)gen;
        while (d_psync[p] < tgt) { __nanosleep(30); }
    }
    __syncthreads();
}

// ---------------- per-launch zero of pair-sync state ----------------
__global__ void k_init0() {
    int i = threadIdx.x + blockIdx.x*blockDim.x;
    if (i < GPAIRS) d_psync[i] = 0u;
    if (i < GPAIRS*SEQs*RPB) d_pairArg[i] = 0ull;
}

// ---------------- grammar w masks ----------------
__global__ void k_w(const int* __restrict__ gg) {
    int tb = blockIdx.x;
    int t = tb / Bb, b = tb % Bb;
    int tid = threadIdx.x;
    __shared__ unsigned char ws[Vv];
    __shared__ int f0;
    for (int v = tid; v < Vv; v += 64) ws[v] = 0;
    if (tid == 0) f0 = 0;
    __syncthreads();
    if (tid < OPTo) {
        int base = ((b*OPTo + tid)*4)*SEQs + t;
        int sym = gg[base];
        int m   = gg[base + 3*SEQs];
        if (m) { if (sym > 0) ws[sym] = 1; else f0 = 1; }
    }
    __syncthreads();
    if (tid == 0) ws[0] = (unsigned char)f0;
    __syncthreads();
    unsigned char* outp = d_w + (size_t)tb*Vv;
    for (int v = tid; v < Vv; v += 64) outp[v] = ws[v];
}

// ---------------- copy small outputs ----------------
__global__ void k_copy(const int* __restrict__ lhs, const int* __restrict__ lmask,
                       const int* __restrict__ gg, float* __restrict__ out) {
    for (int i = blockIdx.x*blockDim.x + threadIdx.x; i < OFF_OPT; i += gridDim.x*blockDim.x) {
        if (i < 256)       out[i] = (float)lhs[i];
        else if (i < 512)  out[i] = (float)lmask[i-256];
        else               out[i] = (float)gg[i-512];
    }
}

// ---------------- prep W: Wtok transpose to (VT,512) bf16 ----------------
__global__ void k_prepW(const float* __restrict__ Wtok) {
    __shared__ float tile[32][33];
    int bi = blockIdx.x;
    int tid = threadIdx.x;
    int tx = tid & 31, ty = tid >> 5;
    int n0 = (bi % 313)*32, k0 = (bi / 313)*32;
    #pragma unroll
    for (int i=0;i<4;i++) {
        int k = k0 + ty + i*8, n = n0 + tx;
        tile[ty+i*8][tx] = (n < VTt) ? Wtok[(size_t)k*VTt + n] : 0.f;
    }
    __syncthreads();
    #pragma unroll
    for (int i=0;i<4;i++) {
        int n = n0 + ty + i*8, k = k0 + tx;
        if (n < VTt)
            d_WhiT[(size_t)n*512 + k] = __float2bfloat16(tile[tx][ty+i*8]);
    }
}

// ============================================================================
// k_steps: 128 blocks (64 pairs x 2 halves), 4 batches/pair, 512 threads.
// Pair splits gx and logits by output columns; exchanges via L2 + pair barrier.
// ============================================================================
#define SM_MEM   0            // 40960
#define SM_GH    40960        // 3072
#define SM_GX    44032        // 3072   (also soa-phase scratch)
#define SM_TS0   47104        // 1024
#define SM_TS    48128        // 1024
#define SM_XP    49152        // 1024  packed [k][4]
#define SM_CATP  50176        // 2048  packed [k][4]
#define SM_SOAP  52224        // 1024  packed [k][4]
#define SM_H     53248        // 1024  unpacked [r][256]
#define SM_ATT   54272        // 160
#define SM_TOT_F 54432
#define SM_BYTES (SM_TOT_F*4)

// full N=768 GEMM (for gh precompute), 2-way k split, float4 stream. ALL threads.
__device__ __forceinline__ void gemm768_ks2(const float* __restrict__ W,
                                            const float* __restrict__ bias,
                                            const float* sXp, float* sOut, int tid) {
    const int active = (tid < 384);
    const int half = (tid >= 192) ? 1 : 0;
    const int c0 = (active ? (half ? tid - 192 : tid) : 0) * 4;
    const int kb = half * 128;
    ull a01[4] = {0,0,0,0}, a23[4] = {0,0,0,0};
    if (active) {
        float4 wA[8], wB[8];
        #pragma unroll
        for (int u=0;u<8;u++) wA[u] = *(const float4*)(W + (size_t)(kb+u)*G3 + c0);
        for (int it = 0; it < 8; ++it) {
            int kA = kb + it*16;
            #pragma unroll
            for (int u=0;u<8;u++) wB[u] = *(const float4*)(W + (size_t)(kA+8+u)*G3 + c0);
            #pragma unroll
            for (int u=0;u<8;u++) {
                ull x01 = *(const ull*)(sXp + (kA+u)*4);
                ull x23 = *(const ull*)(sXp + (kA+u)*4 + 2);
                ull p0 = pk2(wA[u].x,wA[u].x), p1 = pk2(wA[u].y,wA[u].y);
                ull p2 = pk2(wA[u].z,wA[u].z), p3 = pk2(wA[u].w,wA[u].w);
                FMA2(a01[0],x01,p0); FMA2(a23[0],x23,p0);
                FMA2(a01[1],x01,p1); FMA2(a23[1],x23,p1);
                FMA2(a01[2],x01,p2); FMA2(a23[2],x23,p2);
                FMA2(a01[3],x01,p3); FMA2(a23[3],x23,p3);
            }
            int kAn = (it < 7) ? kA + 16 : kb;
            #pragma unroll
            for (int u=0;u<8;u++) wA[u] = *(const float4*)(W + (size_t)(kAn+u)*G3 + c0);
            #pragma unroll
            for (int u=0;u<8;u++) {
                ull x01 = *(const ull*)(sXp + (kA+8+u)*4);
                ull x23 = *(const ull*)(sXp + (kA+8+u)*4 + 2);
                ull p0 = pk2(wB[u].x,wB[u].x), p1 = pk2(wB[u].y,wB[u].y);
                ull p2 = pk2(wB[u].z,wB[u].z), p3 = pk2(wB[u].w,wB[u].w);
                FMA2(a01[0],x01,p0); FMA2(a23[0],x23,p0);
                FMA2(a01[1],x01,p1); FMA2(a23[1],x23,p1);
                FMA2(a01[2],x01,p2); FMA2(a23[2],x23,p2);
                FMA2(a01[3],x01,p3); FMA2(a23[3],x23,p3);
            }
        }
    }
    if (active && half) {
        #pragma unroll
        for (int j=0;j<4;j++) {
            float2 p01 = up2(a01[j]), p23 = up2(a23[j]);
            sOut[0*G3+c0+j] = p01.x; sOut[1*G3+c0+j] = p01.y;
            sOut[2*G3+c0+j] = p23.x; sOut[3*G3+c0+j] = p23.y;
        }
    }
    __syncthreads();
    if (active && !half) {
        #pragma unroll
        for (int j=0;j<4;j++) {
            float bv = bias[c0+j];
            float2 p01 = up2(a01[j]), p23 = up2(a23[j]);
            sOut[0*G3+c0+j] = sOut[0*G3+c0+j] + p01.x + bv;
            sOut[1*G3+c0+j] = sOut[1*G3+c0+j] + p01.y + bv;
            sOut[2*G3+c0+j] = sOut[2*G3+c0+j] + p23.x + bv;
            sOut[3*G3+c0+j] = sOut[3*G3+c0+j] + p23.y + bv;
        }
    }
    __syncthreads();
}

// half-N (384 cols) GEMM for gx: cols [base, base+384), float2 stream,
// 2-way k split (threads 0..191 k-lo, 192..383 k-hi). Writes final values to
// sGx AND gOut (global exchange). Call from ALL threads.
__device__ __forceinline__ void gemm384_half(const float* __restrict__ W,
        const float* __restrict__ bias, const float* sXp, float* sGx,
        float* __restrict__ gOut, int base, int tid) {
    const int active = (tid < 384);
    const int half = (tid >= 192) ? 1 : 0;
    const int ci = active ? (half ? tid - 192 : tid) : 0;
    const int c0 = base + ci*2;
    const int kb = half * 128;
    ull a01[2] = {0,0}, a23[2] = {0,0};
    if (active) {
        float2 wA[8], wB[8];
        #pragma unroll
        for (int u=0;u<8;u++) wA[u] = *(const float2*)(W + (size_t)(kb+u)*G3 + c0);
        for (int it = 0; it < 8; ++it) {
            int kA = kb + it*16;
            #pragma unroll
            for (int u=0;u<8;u++) wB[u] = *(const float2*)(W + (size_t)(kA+8+u)*G3 + c0);
            #pragma unroll
            for (int u=0;u<8;u++) {
                ull x01 = *(const ull*)(sXp + (kA+u)*4);
                ull x23 = *(const ull*)(sXp + (kA+u)*4 + 2);
                ull p0 = pk2(wA[u].x,wA[u].x), p1 = pk2(wA[u].y,wA[u].y);
                FMA2(a01[0],x01,p0); FMA2(a23[0],x23,p0);
                FMA2(a01[1],x01,p1); FMA2(a23[1],x23,p1);
            }
            int kAn = (it < 7) ? kA + 16 : kb;
            #pragma unroll
            for (int u=0;u<8;u++) wA[u] = *(const float2*)(W + (size_t)(kAn+u)*G3 + c0);
            #pragma unroll
            for (int u=0;u<8;u++) {
                ull x01 = *(const ull*)(sXp + (kA+8+u)*4);
                ull x23 = *(const ull*)(sXp + (kA+8+u)*4 + 2);
                ull p0 = pk2(wB[u].x,wB[u].x), p1 = pk2(wB[u].y,wB[u].y);
                FMA2(a01[0],x01,p0); FMA2(a23[0],x23,p0);
                FMA2(a01[1],x01,p1); FMA2(a23[1],x23,p1);
            }
        }
    }
    if (active && half) {
        #pragma unroll
        for (int j=0;j<2;j++) {
            float2 p01 = up2(a01[j]), p23 = up2(a23[j]);
            sGx[0*G3+c0+j] = p01.x; sGx[1*G3+c0+j] = p01.y;
            sGx[2*G3+c0+j] = p23.x; sGx[3*G3+c0+j] = p23.y;
        }
    }
    __syncthreads();
    if (active && !half) {
        #pragma unroll
        for (int j=0;j<2;j++) {
            float bv = bias[c0+j];
            float2 p01 = up2(a01[j]), p23 = up2(a23[j]);
            float v0 = sGx[0*G3+c0+j] + p01.x + bv;
            float v1 = sGx[1*G3+c0+j] + p01.y + bv;
            float v2 = sGx[2*G3+c0+j] + p23.x + bv;
            float v3 = sGx[3*G3+c0+j] + p23.y + bv;
            sGx[0*G3+c0+j] = v0; sGx[1*G3+c0+j] = v1;
            sGx[2*G3+c0+j] = v2; sGx[3*G3+c0+j] = v3;
            gOut[0*G3+c0+j] = v0; gOut[1*G3+c0+j] = v1;
            gOut[2*G3+c0+j] = v2; gOut[3*G3+c0+j] = v3;
        }
    }
}

__global__ __launch_bounds__(THR) void k_steps(
    const int* __restrict__ lhs, const float* __restrict__ ts0,
    const float* __restrict__ emb, const float* __restrict__ mem,
    const float* __restrict__ Wx, const float* __restrict__ bx,
    const float* __restrict__ Wh, const float* __restrict__ bh,
    const float* __restrict__ Wc, const float* __restrict__ bc,
    const float* __restrict__ Wsym, const float* __restrict__ bsym)
{
    extern __shared__ float sm[];
    float* sMem  = sm + SM_MEM;
    float* sGh   = sm + SM_GH;
    float* sGx   = sm + SM_GX;
    float* sTs0  = sm + SM_TS0;
    float* sTs   = sm + SM_TS;
    float* sXp   = sm + SM_XP;
    float* sCatP = sm + SM_CATP;
    float* sSoaP = sm + SM_SOAP;
    float* sH    = sm + SM_H;
    float* sAtt  = sm + SM_ATT;
    __shared__ int sPrev[RPB];
    __shared__ ull sArg[RPB];

    const int tid = threadIdx.x;
    const int lane = tid & 31, warp = tid >> 5;
    const int p  = blockIdx.x >> 1;
    const int h  = blockIdx.x & 1;
    const int b0 = p * RPB;
    const float LT = logf(1e-13f);
    float* gEx = d_gxg + p*RPB*G3;
    int gen = 0;

    // ---- prologue
    {
        const float4* m4 = (const float4*)(mem + (size_t)b0*SRCs*Dd);
        float4* s4 = (float4*)sMem;
        for (int i = tid; i < RPB*SRCs*Dd/4; i += THR) s4[i] = m4[i];
    }
    for (int i = tid; i < RPB*Dd; i += THR) {
        float v = ts0[b0*Dd + i];
        sTs0[i] = v; sTs[i] = v;
        sXp[(i & 255)*4 + (i >> 8)] = v;
    }
    if (tid < RPB) { sPrev[tid] = lhs[b0 + tid]; sArg[tid] = 0ull; }
    __syncthreads();

    // gh = ts0 @ Wh + bh (constant; duplicated in both halves)
    gemm768_ks2(Wh, bh, sXp, sGh, tid);

    // ---- 10 steps
    for (int t = 0; t < SEQs; t++) {
        // gather x = emb[prev] packed (duplicated)
        if (tid < 256) {
            int r = tid >> 6, q = tid & 63;
            float4 v = *(const float4*)(emb + (size_t)sPrev[r]*Dd + q*4);
            sXp[(q*4+0)*4 + r] = v.x;
            sXp[(q*4+1)*4 + r] = v.y;
            sXp[(q*4+2)*4 + r] = v.z;
            sXp[(q*4+3)*4 + r] = v.w;
        }
        __syncthreads();

        // gx half: cols [h*384, h*384+384)
        gemm384_half(Wx, bx, sXp, sGx, gEx, h*384, tid);
        psync(p, ++gen);
        // fetch partner half (L1-bypass: buffer address reused every step)
        {
            int ob = (1 - h)*384;
            if (tid < 384) {
                int c = ob + tid;
                sGx[0*G3+c] = __ldcg(gEx + 0*G3 + c);
                sGx[1*G3+c] = __ldcg(gEx + 1*G3 + c);
                sGx[2*G3+c] = __ldcg(gEx + 2*G3 + c);
                sGx[3*G3+c] = __ldcg(gEx + 3*G3 + c);
            }
        }
        __syncthreads();

        // GRU gates -> h (duplicated)
        {
            int j = tid & 255, rr = tid >> 8;
            #pragma unroll
            for (int q = 0; q < 2; q++) {
                int r = rr*2 + q;
                float xr = sGx[r*G3 + j], xz = sGx[r*G3 + 256 + j], xn = sGx[r*G3 + 512 + j];
                float hr = sGh[r*G3 + j], hz = sGh[r*G3 + 256 + j], hn = sGh[r*G3 + 512 + j];
                float rg = 1.f/(1.f + expf(-(xr+hr)));
                float z  = 1.f/(1.f + expf(-(xz+hz)));
                float n  = tanhf(xn + rg*hn);
                float hv = (1.f - z)*n + z*sTs0[r*Dd + j];
                sH[r*256 + j] = hv;
                sCatP[(256 + j)*4 + r] = hv;
            }
        }
        __syncthreads();

        // attention dots (duplicated)
        for (int d = warp; d < RPB*SRCs; d += 16) {
            int r = d / SRCs, s = d % SRCs;
            const float* hrow = sH + r*256;
            const float* mrow = sMem + (r*SRCs + s)*Dd;
            float sum = 0.f;
            #pragma unroll
            for (int k = 0; k < 8; k++) sum += hrow[lane + k*32]*mrow[lane + k*32];
            #pragma unroll
            for (int o=16;o;o>>=1) sum += __shfl_down_sync(0xffffffffu, sum, o);
            if (lane == 0) sAtt[r*SRCs + s] = sum;
        }
        __syncthreads();

        // softmax (warps 0..3)
        if (warp < RPB) {
            int r = warp;
            float v0 = sAtt[r*SRCs + lane];
            float v1 = (lane < 8) ? sAtt[r*SRCs + 32 + lane] : -1e30f;
            float m = fmaxf(v0, v1);
            #pragma unroll
            for (int o=16;o;o>>=1) m = fmaxf(m, __shfl_xor_sync(0xffffffffu, m, o));
            float e0 = expf(v0 - m);
            float e1 = (lane < 8) ? expf(v1 - m) : 0.f;
            float s = e0 + e1;
            #pragma unroll
            for (int o=16;o;o>>=1) s += __shfl_xor_sync(0xffffffffu, s, o);
            float inv = 1.f/s;
            sAtt[r*SRCs + lane] = e0*inv;
            if (lane < 8) sAtt[r*SRCs + 32 + lane] = e1*inv;
        }
        __syncthreads();

        // ctx packed (duplicated)
        {
            int j = tid & 255, rr = tid >> 8;
            #pragma unroll
            for (int q = 0; q < 2; q++) {
                int r = rr*2 + q;
                float cx = 0.f;
                #pragma unroll 8
                for (int s=0;s<SRCs;s++) cx += sAtt[r*SRCs + s]*sMem[(r*SRCs + s)*Dd + j];
                sCatP[j*4 + r] = cx;
            }
        }
        __syncthreads();

        // soa = tanh(cat @ Wc + bc); duplicated (smallest GEMM); 4-way k-split
        {
            const int sp = tid >> 7;
            const int cg = tid & 127;
            const int c0 = cg*2;
            const int kb = sp*128;
            ull a01[2] = {0,0}, a23[2] = {0,0};
            {
                float2 wA[8], wB[8];
                #pragma unroll
                for (int u=0;u<8;u++) wA[u] = *(const float2*)(Wc + (size_t)(kb+u)*Dd + c0);
                for (int it = 0; it < 8; ++it) {
                    int kA = kb + it*16;
                    #pragma unroll
                    for (int u=0;u<8;u++) wB[u] = *(const float2*)(Wc + (size_t)(kA+8+u)*Dd + c0);
                    #pragma unroll
                    for (int u=0;u<8;u++) {
                        ull x01 = *(const ull*)(sCatP + (kA+u)*4);
                        ull x23 = *(const ull*)(sCatP + (kA+u)*4 + 2);
                        ull p0 = pk2(wA[u].x,wA[u].x), p1 = pk2(wA[u].y,wA[u].y);
                        FMA2(a01[0],x01,p0); FMA2(a23[0],x23,p0);
                        FMA2(a01[1],x01,p1); FMA2(a23[1],x23,p1);
                    }
                    int kAn = (it < 7) ? kA + 16 : kb;
                    #pragma unroll
                    for (int u=0;u<8;u++) wA[u] = *(const float2*)(Wc + (size_t)(kAn+u)*Dd + c0);
                    #pragma unroll
                    for (int u=0;u<8;u++) {
                        ull x01 = *(const ull*)(sCatP + (kA+8+u)*4);
                        ull x23 = *(const ull*)(sCatP + (kA+8+u)*4 + 2);
                        ull p0 = pk2(wB[u].x,wB[u].x), p1 = pk2(wB[u].y,wB[u].y);
                        FMA2(a01[0],x01,p0); FMA2(a23[0],x23,p0);
                        FMA2(a01[1],x01,p1); FMA2(a23[1],x23,p1);
                    }
                }
            }
            if (sp > 0) {
                float* scr = sGx + (sp-1)*1024;
                #pragma unroll
                for (int j=0;j<2;j++) {
                    float2 p01 = up2(a01[j]), p23 = up2(a23[j]);
                    scr[(c0+j)*4+0] = p01.x; scr[(c0+j)*4+1] = p01.y;
                    scr[(c0+j)*4+2] = p23.x; scr[(c0+j)*4+3] = p23.y;
                }
            }
            __syncthreads();
            if (sp == 0) {
                #pragma unroll
                for (int j=0;j<2;j++) {
                    float2 p01 = up2(a01[j]), p23 = up2(a23[j]);
                    float v[4] = {p01.x, p01.y, p23.x, p23.y};
                    float bcv = bc[c0+j];
                    #pragma unroll
                    for (int r=0;r<4;r++) {
                        float sum = v[r] + sGx[0*1024+(c0+j)*4+r]
                                         + sGx[1*1024+(c0+j)*4+r]
                                         + sGx[2*1024+(c0+j)*4+r] + bcv;
                        float s = tanhf(sum);
                        sSoaP[(c0+j)*4+r] = s;
                        if (h == 0) sTs[r*256+c0+j] = tanhf(sTs[r*256+c0+j] + s);
                    }
                }
            }
            __syncthreads();
        }

        // logits half: cols [h*1000, h*1000+1000); float2 stream; argmax
        {
            ull best[RPB] = {0ull,0ull,0ull,0ull};
            if (tid < 500) {
                int c0 = h*1000 + tid*2;
                ull a01[2] = {0,0}, a23[2] = {0,0};
                float2 wA[8], wB[8];
                #pragma unroll
                for (int u=0;u<8;u++) wA[u] = *(const float2*)(Wsym + (size_t)u*Vv + c0);
                for (int it = 0; it < 16; ++it) {
                    int kA = it*16;
                    #pragma unroll
                    for (int u=0;u<8;u++) wB[u] = *(const float2*)(Wsym + (size_t)(kA+8+u)*Vv + c0);
                    #pragma unroll
                    for (int u=0;u<8;u++) {
                        ull x01 = *(const ull*)(sSoaP + (kA+u)*4);
                        ull x23 = *(const ull*)(sSoaP + (kA+u)*4 + 2);
                        ull p0 = pk2(wA[u].x,wA[u].x), p1 = pk2(wA[u].y,wA[u].y);
                        FMA2(a01[0],x01,p0); FMA2(a23[0],x23,p0);
                        FMA2(a01[1],x01,p1); FMA2(a23[1],x23,p1);
                    }
                    int kAn = (it < 15) ? kA + 16 : 0;
                    #pragma unroll
                    for (int u=0;u<8;u++) wA[u] = *(const float2*)(Wsym + (size_t)(kAn+u)*Vv + c0);
                    #pragma unroll
                    for (int u=0;u<8;u++) {
                        ull x01 = *(const ull*)(sSoaP + (kA+8+u)*4);
                        ull x23 = *(const ull*)(sSoaP + (kA+8+u)*4 + 2);
                        ull p0 = pk2(wB[u].x,wB[u].x), p1 = pk2(wB[u].y,wB[u].y);
                        FMA2(a01[0],x01,p0); FMA2(a23[0],x23,p0);
                        FMA2(a01[1],x01,p1); FMA2(a23[1],x23,p1);
                    }
                }
                float2 bs = *(const float2*)(bsym + c0);
                float vb[2] = {bs.x, bs.y};
                float vr[RPB][2];
                #pragma unroll
                for (int j=0;j<2;j++) {
                    float2 p01 = up2(a01[j]), p23 = up2(a23[j]);
                    vr[0][j] = p01.x + vb[j];
                    vr[1][j] = p01.y + vb[j];
                    vr[2][j] = p23.x + vb[j];
                    vr[3][j] = p23.y + vb[j];
                }
                #pragma unroll
                for (int r=0;r<RPB;r++) {
                    int row = t*Bb + b0 + r;
                    uchar2 wm = *(const uchar2*)(d_w + (size_t)row*Vv + c0);
                    unsigned char wmv[2] = {wm.x, wm.y};
                    float2 st;
                    float* stp = &st.x;
                    #pragma unroll
                    for (int j=0;j<2;j++) {
                        float v = vr[r][j];
                        if (!wmv[j]) v += LT;
                        stp[j] = v;
                        ull key = ((ull)f2mono(v) << 32) | (0xFFFFFFFFu - (unsigned)(c0 + j));
                        if (key > best[r]) best[r] = key;
                    }
                    *(float2*)(d_clog + (size_t)row*Vv + c0) = st;
                }
            }
            #pragma unroll
            for (int r=0;r<RPB;r++) {
                ull bv = best[r];
                #pragma unroll
                for (int o=16;o;o>>=1) {
                    ull x = __shfl_xor_sync(0xffffffffu, bv, o);
                    if (x > bv) bv = x;
                }
                if (lane == 0 && bv) atomicMax(&sArg[r], bv);
            }
        }
        __syncthreads();
        // cross-block argmax combine
        if (tid < RPB) atomicMax(&d_pairArg[(p*SEQs + t)*RPB + tid], sArg[tid]);
        psync(p, ++gen);
        if (tid < RPB) {
            ull k = *((volatile ull*)&d_pairArg[(p*SEQs + t)*RPB + tid]);
            sPrev[tid] = (int)(0xFFFFFFFFu - (unsigned)(k & 0xFFFFFFFFull));
            sArg[tid] = 0ull;
        }
        __syncthreads();
    }

    if (h == 0) {
        for (int i = tid; i < RPB*Dd; i += THR)
            d_ts[b0*Dd + i] = sTs[i];
    }
}

// ============================================================================
// k_tail: per-batch lse + opts + topo + prepA. grid=256.
// ============================================================================
__global__ __launch_bounds__(256) void k_tail(const int* __restrict__ gg,
                                              const float* __restrict__ emb,
                                              float* __restrict__ out)
{
    const int b = blockIdx.x;
    const int tid = threadIdx.x;
    const int lane = tid & 31, warp = tid >> 5;
    __shared__ float sLse[SEQs];
    __shared__ float sVals[OPTo*SEQs];
    __shared__ float sSol[OPTo];
    __shared__ int   sBest;
    __shared__ int   sSym[SEQs];

    for (int t = warp; t < SEQs; t += 8) {
        const float* row = d_clog + ((size_t)t*Bb + b)*Vv;
        float m = -1e30f;
        for (int v = lane; v < Vv; v += 32) m = fmaxf(m, row[v]);
        #pragma unroll
        for (int o=16;o;o>>=1) m = fmaxf(m, __shfl_xor_sync(0xffffffffu, m, o));
        float s = 0.f;
        for (int v = lane; v < Vv; v += 32) s += expf(row[v]-m);
        #pragma unroll
        for (int o=16;o;o>>=1) s += __shfl_xor_sync(0xffffffffu, s, o);
        if (lane == 0) sLse[t] = m + logf(s);
    }
    __syncthreads();
    if (tid < OPTo*SEQs) {
        int o = tid / SEQs, t = tid % SEQs;
        int base = ((b*OPTo + o)*4)*SEQs + t;
        int m = gg[base + 3*SEQs];
        float v = 0.f;
        if (m) {
            int sym = gg[base];
            v = logf(expf(d_clog[((size_t)t*Bb + b)*Vv + sym] - sLse[t]) + 1e-13f);
        }
        sVals[tid] = v;
    }
    __syncthreads();
    if (tid < OPTo) {
        float s = 0.f;
        #pragma unroll
        for (int t=0;t<SEQs;t++) s += sVals[tid*SEQs + t];
        sSol[tid] = s;
        out[OFF_OPT + b*OPTo + tid] = s;
    }
    __syncthreads();
    if (tid == 0) {
        int bi = 0; float bv = sSol[0];
        for (int o=1;o<OPTo;o++) if (sSol[o] > bv) { bv = sSol[o]; bi = o; }
        sBest = bi;
    }
    __syncthreads();
    if (tid < 4*SEQs) {
        int c = tid / SEQs, s = tid % SEQs;
        int val = gg[((b*OPTo + sBest)*4 + c)*SEQs + s];
        out[OFF_TOPO + c*(Bb*SEQs) + b*SEQs + s] = (float)val;
        if (c == 0) { sSym[s] = val; d_sym[b*SEQs + s] = val; }
    }
    __syncthreads();
    for (int i = tid; i < SEQs*512; i += 256) {
        int s = i >> 9, k = i & 511;
        float v = (k < Dd) ? emb[(size_t)sSym[s]*Dd + k] : d_ts[b*Dd + (k - Dd)];
        d_Ahi[((size_t)b*SEQs + s)*512 + k] = __float2bfloat16(v);
    }
}

// ---------------- exact_logit GEMM: single bf16 mma, 128x128x32, double-buffered --
#define MMA16816(d, a, b) asm volatile( \
    "mma.sync.aligned.m16n8k16.row.col.f32.bf16.bf16.f32 " \
    "{%0,%1,%2,%3}, {%4,%5,%6,%7}, {%8,%9}, {%0,%1,%2,%3};\n" \
    : "+f"(d[0]), "+f"(d[1]), "+f"(d[2]), "+f"(d[3]) \
    : "r"(a[0]), "r"(a[1]), "r"(a[2]), "r"(a[3]), "r"(b[0]), "r"(b[1]))

#define XSTR 40

__global__ __launch_bounds__(256) void k_exact(const float* __restrict__ btok,
                                               const float* __restrict__ tok,
                                               float* __restrict__ out) {
    __shared__ __nv_bfloat16 sA[2][128*XSTR], sB[2][128*XSTR];
    int tid = threadIdx.x;
    int m0 = blockIdx.y*128, n0 = blockIdx.x*128;
    int lane = tid & 31, warp = tid >> 5;
    int wm = warp >> 2, wn = warp & 3;
    int g = lane >> 2, tq = lane & 3;
    float acc[4][4][4];
    #pragma unroll
    for (int i=0;i<4;i++) {
        #pragma unroll
        for (int j=0;j<4;j++) {
            #pragma unroll
            for (int q=0;q<4;q++) acc[i][j][q] = 0.f;
        }
    }

    int row = tid >> 1;
    int kh  = (tid & 1) << 4;
    int nr  = n0 + row;
    const bool nok = (nr < VTt);

    uint4 ra0, ra1, rb0, rb1;
    const uint4 z0 = make_uint4(0,0,0,0);

    {
        const uint4* p = (const uint4*)(d_Ahi + (size_t)(m0+row)*512 + kh);
        ra0 = p[0]; ra1 = p[1];
        rb0 = z0; rb1 = z0;
        if (nok) {
            const uint4* q = (const uint4*)(d_WhiT + (size_t)nr*512 + kh);
            rb0 = q[0]; rb1 = q[1];
        }
    }
    *(uint4*)&sA[0][row*XSTR + kh]     = ra0;
    *(uint4*)&sA[0][row*XSTR + kh + 8] = ra1;
    *(uint4*)&sB[0][row*XSTR + kh]     = rb0;
    *(uint4*)&sB[0][row*XSTR + kh + 8] = rb1;
    __syncthreads();

    int buf = 0;
    for (int k0 = 0; k0 < 512; k0 += 32) {
        int nxt = k0 + 32;
        if (nxt < 512) {
            const uint4* p = (const uint4*)(d_Ahi + (size_t)(m0+row)*512 + nxt + kh);
            ra0 = p[0]; ra1 = p[1];
            rb0 = z0; rb1 = z0;
            if (nok) {
                const uint4* q = (const uint4*)(d_WhiT + (size_t)nr*512 + nxt + kh);
                rb0 = q[0]; rb1 = q[1];
            }
        }
        const __nv_bfloat16* cA = sA[buf];
        const __nv_bfloat16* cB = sB[buf];
        #pragma unroll
        for (int ks = 0; ks < 2; ks++) {
            int kb = ks*16;
            uint32_t ah[4][4];
            #pragma unroll
            for (int mi=0;mi<4;mi++) {
                int rb = wm*64 + mi*16;
                int c0 = kb + tq*2;
                ah[mi][0] = *(const uint32_t*)&cA[(rb+g)*XSTR + c0];
                ah[mi][1] = *(const uint32_t*)&cA[(rb+g+8)*XSTR + c0];
                ah[mi][2] = *(const uint32_t*)&cA[(rb+g)*XSTR + c0 + 8];
                ah[mi][3] = *(const uint32_t*)&cA[(rb+g+8)*XSTR + c0 + 8];
            }
            uint32_t bh[4][2];
            #pragma unroll
            for (int ni=0;ni<4;ni++) {
                int nb = wn*32 + ni*8 + g;
                bh[ni][0] = *(const uint32_t*)&cB[nb*XSTR + kb + tq*2];
                bh[ni][1] = *(const uint32_t*)&cB[nb*XSTR + kb + tq*2 + 8];
            }
            #pragma unroll
            for (int mi=0;mi<4;mi++) {
                #pragma unroll
                for (int ni=0;ni<4;ni++) {
                    MMA16816(acc[mi][ni], ah[mi], bh[ni]);
                }
            }
        }
        if (nxt < 512) {
            *(uint4*)&sA[buf^1][row*XSTR + kh]     = ra0;
            *(uint4*)&sA[buf^1][row*XSTR + kh + 8] = ra1;
            *(uint4*)&sB[buf^1][row*XSTR + kh]     = rb0;
            *(uint4*)&sB[buf^1][row*XSTR + kh + 8] = rb1;
            __syncthreads();
            buf ^= 1;
        }
    }

    const float LT = logf(1e-13f);
    #pragma unroll
    for (int mi=0;mi<4;mi++) {
        int r0 = m0 + wm*64 + mi*16 + g;
        int s0 = d_sym[r0];
        int s1 = d_sym[r0 + 8];
        #pragma unroll
        for (int ni=0;ni<4;ni++) {
            int c0 = n0 + wn*32 + ni*8 + tq*2;
            if (c0 < VTt) {
                float b0 = btok[c0];
                out[OFF_EX + (size_t)r0*VTt + c0]     = acc[mi][ni][0] + b0 + (tok[(size_t)s0*VTt + c0] > 0.f ? 0.f : LT);
                out[OFF_EX + (size_t)(r0+8)*VTt + c0] = acc[mi][ni][2] + b0 + (tok[(size_t)s1*VTt + c0] > 0.f ? 0.f : LT);
            }
            if (c0 + 1 < VTt) {
                float b1 = btok[c0+1];
                out[OFF_EX + (size_t)r0*VTt + c0+1]     = acc[mi][ni][1] + b1 + (tok[(size_t)s0*VTt + c0+1] > 0.f ? 0.f : LT);
                out[OFF_EX + (size_t)(r0+8)*VTt + c0+1] = acc[mi][ni][3] + b1 + (tok[(size_t)s1*VTt + c0+1] > 0.f ? 0.f : LT);
            }
        }
    }
}

// ---------------- host launcher ----------------
extern "C" void kernel_launch(void* const* d_in, const int* in_sizes, int n_in,
                              void* d_out, int out_size) {
    const int*   lhs   = (const int*)d_in[0];
    const int*   lmask = (const int*)d_in[1];
    const float* ts0   = (const float*)d_in[2];
    const int*   gg    = (const int*)d_in[3];
    const float* emb   = (const float*)d_in[4];
    const float* mem   = (const float*)d_in[5];
    const float* Wx    = (const float*)d_in[6];
    const float* Wh    = (const float*)d_in[7];
    const float* bx    = (const float*)d_in[8];
    const float* bh    = (const float*)d_in[9];
    const float* Wc    = (const float*)d_in[10];
    const float* bc    = (const float*)d_in[11];
    const float* Wsym  = (const float*)d_in[12];
    const float* bsym  = (const float*)d_in[13];
    const float* Wtok  = (const float*)d_in[14];
    const float* btok  = (const float*)d_in[15];
    const float* tok   = (const float*)d_in[16];
    float* out = (float*)d_out;

    static bool attr_set = false;
    if (!attr_set) {
        cudaFuncSetAttribute(k_steps, cudaFuncAttributeMaxDynamicSharedMemorySize, SM_BYTES);
        attr_set = true;
    }

    k_init0<<<10, 256>>>();
    k_w<<<SEQs*Bb, 64>>>(gg);
    k_prepW<<<5008, 256>>>(Wtok);
    k_copy<<<642, 256>>>(lhs, lmask, gg, out);
    k_steps<<<GSTEP, THR, SM_BYTES>>>(lhs, ts0, emb, mem, Wx, bx, Wh, bh, Wc, bc, Wsym, bsym);
    k_tail<<<Bb, 256>>>(gg, emb, out);
    k_exact<<<dim3((VTt+127)/128, (Bb*SEQs)/128), 256>>>(btok, tok, out);
}

// round 17
// speedup vs baseline: 1.6658x; 1.0292x over previous
#include <cuda_runtime.h>
#include <cuda_bf16.h>
#include <cstdint>

#define Bb   256
#define Dd   256
#define Vv   2000
#define VTt  10000
#define OPTo 16
#define SEQs 10
#define SRCs 40
#define G3   768
#define GPAIRS 64
#define GSTEP 128
#define RPB   4
#define THR   512

#define OFF_OPT  164352
#define OFF_TOPO 168448
#define OFF_EX   178688

typedef unsigned long long ull;

// ---------------- device scratch ----------------
__device__ float d_ts[Bb*Dd];
__device__ float d_clog[SEQs*Bb*Vv];
__device__ unsigned char d_w[SEQs*Bb*Vv];
__device__ int   d_sym[Bb*SEQs];
__device__ float d_gxg[GPAIRS*RPB*G3];
__device__ ull   d_pairArg[GPAIRS*SEQs*RPB];
__device__ volatile unsigned d_psync[GPAIRS];
__device__ __nv_bfloat16 d_Ahi[Bb*SEQs*2*Dd];
__device__ __nv_bfloat16 d_WhiT[(size_t)VTt*2*Dd];

__device__ __forceinline__ unsigned f2mono(float f) {
    unsigned u = __float_as_uint(f);
    return (u & 0x80000000u) ? ~u : (u | 0x80000000u);
}

// packed f32x2 helpers (sm_103a)
#define FMA2(d, a, b) asm("fma.rn.f32x2 %0, %1, %2, %0;" : "+l"(d) : "l"(a), "l"(b))
__device__ __forceinline__ ull pk2(float x, float y) {
    ull r;
    asm("mov.b64 %0, {%1,%2};" : "=l"(r) : "f"(x), "f"(y));
    return r;
}
__device__ __forceinline__ float2 up2(ull v) {
    float2 r;
    asm("mov.b64 {%0,%1}, %2;" : "=f"(r.x), "=f"(r.y) : "l"(v));
    return r;
}

// pair barrier: both blocks of pair p call with identical gen sequence (1,2,3,...)
__device__ __forceinline__ void psync(int p, int gen) {
    __threadfence();
    __syncthreads();
    if (threadIdx.x == 0) {
        atomicAdd((unsigned*)&d_psync[p], 1u);
        unsigned tgt = 2u*(unsigned)gen;
        while (d_psync[p] < tgt) { __nanosleep(30); }
    }
    __syncthreads();
}

// ---------------- grammar w masks (+ per-launch zero of pair-sync state) -----
__global__ void k_w(const int* __restrict__ gg) {
    int tb = blockIdx.x;
    int t = tb / Bb, b = tb % Bb;
    int tid = threadIdx.x;
    // zero pair-sync state (replay safety) using first blocks
    if (tb == 0 && tid < GPAIRS) d_psync[tid] = 0u;
    if (tb < 40) {
        int i = tb*64 + tid;
        if (i < GPAIRS*SEQs*RPB) d_pairArg[i] = 0ull;
    }
    __shared__ unsigned char ws[Vv];
    __shared__ int f0;
    for (int v = tid; v < Vv; v += 64) ws[v] = 0;
    if (tid == 0) f0 = 0;
    __syncthreads();
    if (tid < OPTo) {
        int base = ((b*OPTo + tid)*4)*SEQs + t;
        int sym = gg[base];
        int m   = gg[base + 3*SEQs];
        if (m) { if (sym > 0) ws[sym] = 1; else f0 = 1; }
    }
    __syncthreads();
    if (tid == 0) ws[0] = (unsigned char)f0;
    __syncthreads();
    unsigned char* outp = d_w + (size_t)tb*Vv;
    for (int v = tid; v < Vv; v += 64) outp[v] = ws[v];
}

// ---------------- copy small outputs ----------------
__global__ void k_copy(const int* __restrict__ lhs, const int* __restrict__ lmask,
                       const int* __restrict__ gg, float* __restrict__ out) {
    for (int i = blockIdx.x*blockDim.x + threadIdx.x; i < OFF_OPT; i += gridDim.x*blockDim.x) {
        if (i < 256)       out[i] = (float)lhs[i];
        else if (i < 512)  out[i] = (float)lmask[i-256];
        else               out[i] = (float)gg[i-512];
    }
}

// ---------------- prep W: Wtok transpose to (VT,512) bf16 ----------------
__global__ void k_prepW(const float* __restrict__ Wtok) {
    __shared__ float tile[32][33];
    int bi = blockIdx.x;
    int tid = threadIdx.x;
    int tx = tid & 31, ty = tid >> 5;
    int n0 = (bi % 313)*32, k0 = (bi / 313)*32;
    #pragma unroll
    for (int i=0;i<4;i++) {
        int k = k0 + ty + i*8, n = n0 + tx;
        tile[ty+i*8][tx] = (n < VTt) ? Wtok[(size_t)k*VTt + n] : 0.f;
    }
    __syncthreads();
    #pragma unroll
    for (int i=0;i<4;i++) {
        int n = n0 + ty + i*8, k = k0 + tx;
        if (n < VTt)
            d_WhiT[(size_t)n*512 + k] = __float2bfloat16(tile[tx][ty+i*8]);
    }
}

// ============================================================================
// k_steps: 128 blocks (64 pairs x 2 halves), 4 batches/pair, 512 threads.
// ============================================================================
#define SM_MEM   0            // 40960
#define SM_GH    40960        // 3072
#define SM_GX    44032        // 3072   (also soa-phase scratch)
#define SM_TS0   47104        // 1024
#define SM_TS    48128        // 1024
#define SM_XP    49152        // 1024  packed [k][4]
#define SM_CATP  50176        // 2048  packed [k][4]
#define SM_SOAP  52224        // 1024  packed [k][4]
#define SM_H     53248        // 1024  unpacked [r][256]
#define SM_ATT   54272        // 160
#define SM_TOT_F 54432
#define SM_BYTES (SM_TOT_F*4)

// full N=768 GEMM (for gh precompute), 2-way k split, float4 stream. ALL threads.
__device__ __forceinline__ void gemm768_ks2(const float* __restrict__ W,
                                            const float* __restrict__ bias,
                                            const float* sXp, float* sOut, int tid) {
    const int active = (tid < 384);
    const int half = (tid >= 192) ? 1 : 0;
    const int c0 = (active ? (half ? tid - 192 : tid) : 0) * 4;
    const int kb = half * 128;
    ull a01[4] = {0,0,0,0}, a23[4] = {0,0,0,0};
    if (active) {
        float4 wA[8], wB[8];
        #pragma unroll
        for (int u=0;u<8;u++) wA[u] = *(const float4*)(W + (size_t)(kb+u)*G3 + c0);
        for (int it = 0; it < 8; ++it) {
            int kA = kb + it*16;
            #pragma unroll
            for (int u=0;u<8;u++) wB[u] = *(const float4*)(W + (size_t)(kA+8+u)*G3 + c0);
            #pragma unroll
            for (int u=0;u<8;u++) {
                ull x01 = *(const ull*)(sXp + (kA+u)*4);
                ull x23 = *(const ull*)(sXp + (kA+u)*4 + 2);
                ull p0 = pk2(wA[u].x,wA[u].x), p1 = pk2(wA[u].y,wA[u].y);
                ull p2 = pk2(wA[u].z,wA[u].z), p3 = pk2(wA[u].w,wA[u].w);
                FMA2(a01[0],x01,p0); FMA2(a23[0],x23,p0);
                FMA2(a01[1],x01,p1); FMA2(a23[1],x23,p1);
                FMA2(a01[2],x01,p2); FMA2(a23[2],x23,p2);
                FMA2(a01[3],x01,p3); FMA2(a23[3],x23,p3);
            }
            int kAn = (it < 7) ? kA + 16 : kb;
            #pragma unroll
            for (int u=0;u<8;u++) wA[u] = *(const float4*)(W + (size_t)(kAn+u)*G3 + c0);
            #pragma unroll
            for (int u=0;u<8;u++) {
                ull x01 = *(const ull*)(sXp + (kA+8+u)*4);
                ull x23 = *(const ull*)(sXp + (kA+8+u)*4 + 2);
                ull p0 = pk2(wB[u].x,wB[u].x), p1 = pk2(wB[u].y,wB[u].y);
                ull p2 = pk2(wB[u].z,wB[u].z), p3 = pk2(wB[u].w,wB[u].w);
                FMA2(a01[0],x01,p0); FMA2(a23[0],x23,p0);
                FMA2(a01[1],x01,p1); FMA2(a23[1],x23,p1);
                FMA2(a01[2],x01,p2); FMA2(a23[2],x23,p2);
                FMA2(a01[3],x01,p3); FMA2(a23[3],x23,p3);
            }
        }
    }
    if (active && half) {
        #pragma unroll
        for (int j=0;j<4;j++) {
            float2 p01 = up2(a01[j]), p23 = up2(a23[j]);
            sOut[0*G3+c0+j] = p01.x; sOut[1*G3+c0+j] = p01.y;
            sOut[2*G3+c0+j] = p23.x; sOut[3*G3+c0+j] = p23.y;
        }
    }
    __syncthreads();
    if (active && !half) {
        #pragma unroll
        for (int j=0;j<4;j++) {
            float bv = bias[c0+j];
            float2 p01 = up2(a01[j]), p23 = up2(a23[j]);
            sOut[0*G3+c0+j] = sOut[0*G3+c0+j] + p01.x + bv;
            sOut[1*G3+c0+j] = sOut[1*G3+c0+j] + p01.y + bv;
            sOut[2*G3+c0+j] = sOut[2*G3+c0+j] + p23.x + bv;
            sOut[3*G3+c0+j] = sOut[3*G3+c0+j] + p23.y + bv;
        }
    }
    __syncthreads();
}

// half-N (384 cols) GEMM for gx. Writes sGx AND gOut. ALL threads.
__device__ __forceinline__ void gemm384_half(const float* __restrict__ W,
        const float* __restrict__ bias, const float* sXp, float* sGx,
        float* __restrict__ gOut, int base, int tid) {
    const int active = (tid < 384);
    const int half = (tid >= 192) ? 1 : 0;
    const int ci = active ? (half ? tid - 192 : tid) : 0;
    const int c0 = base + ci*2;
    const int kb = half * 128;
    ull a01[2] = {0,0}, a23[2] = {0,0};
    if (active) {
        float2 wA[8], wB[8];
        #pragma unroll
        for (int u=0;u<8;u++) wA[u] = *(const float2*)(W + (size_t)(kb+u)*G3 + c0);
        for (int it = 0; it < 8; ++it) {
            int kA = kb + it*16;
            #pragma unroll
            for (int u=0;u<8;u++) wB[u] = *(const float2*)(W + (size_t)(kA+8+u)*G3 + c0);
            #pragma unroll
            for (int u=0;u<8;u++) {
                ull x01 = *(const ull*)(sXp + (kA+u)*4);
                ull x23 = *(const ull*)(sXp + (kA+u)*4 + 2);
                ull p0 = pk2(wA[u].x,wA[u].x), p1 = pk2(wA[u].y,wA[u].y);
                FMA2(a01[0],x01,p0); FMA2(a23[0],x23,p0);
                FMA2(a01[1],x01,p1); FMA2(a23[1],x23,p1);
            }
            int kAn = (it < 7) ? kA + 16 : kb;
            #pragma unroll
            for (int u=0;u<8;u++) wA[u] = *(const float2*)(W + (size_t)(kAn+u)*G3 + c0);
            #pragma unroll
            for (int u=0;u<8;u++) {
                ull x01 = *(const ull*)(sXp + (kA+8+u)*4);
                ull x23 = *(const ull*)(sXp + (kA+8+u)*4 + 2);
                ull p0 = pk2(wB[u].x,wB[u].x), p1 = pk2(wB[u].y,wB[u].y);
                FMA2(a01[0],x01,p0); FMA2(a23[0],x23,p0);
                FMA2(a01[1],x01,p1); FMA2(a23[1],x23,p1);
            }
        }
    }
    if (active && half) {
        #pragma unroll
        for (int j=0;j<2;j++) {
            float2 p01 = up2(a01[j]), p23 = up2(a23[j]);
            sGx[0*G3+c0+j] = p01.x; sGx[1*G3+c0+j] = p01.y;
            sGx[2*G3+c0+j] = p23.x; sGx[3*G3+c0+j] = p23.y;
        }
    }
    __syncthreads();
    if (active && !half) {
        #pragma unroll
        for (int j=0;j<2;j++) {
            float bv = bias[c0+j];
            float2 p01 = up2(a01[j]), p23 = up2(a23[j]);
            float v0 = sGx[0*G3+c0+j] + p01.x + bv;
            float v1 = sGx[1*G3+c0+j] + p01.y + bv;
            float v2 = sGx[2*G3+c0+j] + p23.x + bv;
            float v3 = sGx[3*G3+c0+j] + p23.y + bv;
            sGx[0*G3+c0+j] = v0; sGx[1*G3+c0+j] = v1;
            sGx[2*G3+c0+j] = v2; sGx[3*G3+c0+j] = v3;
            gOut[0*G3+c0+j] = v0; gOut[1*G3+c0+j] = v1;
            gOut[2*G3+c0+j] = v2; gOut[3*G3+c0+j] = v3;
        }
    }
}

__global__ __launch_bounds__(THR) void k_steps(
    const int* __restrict__ lhs, const float* __restrict__ ts0,
    const float* __restrict__ emb, const float* __restrict__ mem,
    const float* __restrict__ Wx, const float* __restrict__ bx,
    const float* __restrict__ Wh, const float* __restrict__ bh,
    const float* __restrict__ Wc, const float* __restrict__ bc,
    const float* __restrict__ Wsym, const float* __restrict__ bsym)
{
    extern __shared__ float sm[];
    float* sMem  = sm + SM_MEM;
    float* sGh   = sm + SM_GH;
    float* sGx   = sm + SM_GX;
    float* sTs0  = sm + SM_TS0;
    float* sTs   = sm + SM_TS;
    float* sXp   = sm + SM_XP;
    float* sCatP = sm + SM_CATP;
    float* sSoaP = sm + SM_SOAP;
    float* sH    = sm + SM_H;
    float* sAtt  = sm + SM_ATT;
    __shared__ int sPrev[RPB];
    __shared__ ull sArg[RPB];

    const int tid = threadIdx.x;
    const int lane = tid & 31, warp = tid >> 5;
    const int p  = blockIdx.x >> 1;
    const int h  = blockIdx.x & 1;
    const int b0 = p * RPB;
    const float LT = logf(1e-13f);
    float* gEx = d_gxg + p*RPB*G3;
    int gen = 0;

    // ---- prologue
    {
        const float4* m4 = (const float4*)(mem + (size_t)b0*SRCs*Dd);
        float4* s4 = (float4*)sMem;
        for (int i = tid; i < RPB*SRCs*Dd/4; i += THR) s4[i] = m4[i];
    }
    for (int i = tid; i < RPB*Dd; i += THR) {
        float v = ts0[b0*Dd + i];
        sTs0[i] = v; sTs[i] = v;
        sXp[(i & 255)*4 + (i >> 8)] = v;
    }
    if (tid < RPB) { sPrev[tid] = lhs[b0 + tid]; sArg[tid] = 0ull; }
    __syncthreads();

    // gh = ts0 @ Wh + bh (constant; duplicated in both halves)
    gemm768_ks2(Wh, bh, sXp, sGh, tid);

    // ---- 10 steps
    for (int t = 0; t < SEQs; t++) {
        if (tid < 256) {
            int r = tid >> 6, q = tid & 63;
            float4 v = *(const float4*)(emb + (size_t)sPrev[r]*Dd + q*4);
            sXp[(q*4+0)*4 + r] = v.x;
            sXp[(q*4+1)*4 + r] = v.y;
            sXp[(q*4+2)*4 + r] = v.z;
            sXp[(q*4+3)*4 + r] = v.w;
        }
        __syncthreads();

        // gx half: cols [h*384, h*384+384)
        gemm384_half(Wx, bx, sXp, sGx, gEx, h*384, tid);
        psync(p, ++gen);
        {
            int ob = (1 - h)*384;
            if (tid < 384) {
                int c = ob + tid;
                sGx[0*G3+c] = __ldcg(gEx + 0*G3 + c);
                sGx[1*G3+c] = __ldcg(gEx + 1*G3 + c);
                sGx[2*G3+c] = __ldcg(gEx + 2*G3 + c);
                sGx[3*G3+c] = __ldcg(gEx + 3*G3 + c);
            }
        }
        __syncthreads();

        // GRU gates -> h (duplicated)
        {
            int j = tid & 255, rr = tid >> 8;
            #pragma unroll
            for (int q = 0; q < 2; q++) {
                int r = rr*2 + q;
                float xr = sGx[r*G3 + j], xz = sGx[r*G3 + 256 + j], xn = sGx[r*G3 + 512 + j];
                float hr = sGh[r*G3 + j], hz = sGh[r*G3 + 256 + j], hn = sGh[r*G3 + 512 + j];
                float rg = 1.f/(1.f + expf(-(xr+hr)));
                float z  = 1.f/(1.f + expf(-(xz+hz)));
                float n  = tanhf(xn + rg*hn);
                float hv = (1.f - z)*n + z*sTs0[r*Dd + j];
                sH[r*256 + j] = hv;
                sCatP[(256 + j)*4 + r] = hv;
            }
        }
        __syncthreads();

        // attention dots (duplicated)
        for (int d = warp; d < RPB*SRCs; d += 16) {
            int r = d / SRCs, s = d % SRCs;
            const float* hrow = sH + r*256;
            const float* mrow = sMem + (r*SRCs + s)*Dd;
            float sum = 0.f;
            #pragma unroll
            for (int k = 0; k < 8; k++) sum += hrow[lane + k*32]*mrow[lane + k*32];
            #pragma unroll
            for (int o=16;o;o>>=1) sum += __shfl_down_sync(0xffffffffu, sum, o);
            if (lane == 0) sAtt[r*SRCs + s] = sum;
        }
        __syncthreads();

        // softmax (warps 0..3)
        if (warp < RPB) {
            int r = warp;
            float v0 = sAtt[r*SRCs + lane];
            float v1 = (lane < 8) ? sAtt[r*SRCs + 32 + lane] : -1e30f;
            float m = fmaxf(v0, v1);
            #pragma unroll
            for (int o=16;o;o>>=1) m = fmaxf(m, __shfl_xor_sync(0xffffffffu, m, o));
            float e0 = expf(v0 - m);
            float e1 = (lane < 8) ? expf(v1 - m) : 0.f;
            float s = e0 + e1;
            #pragma unroll
            for (int o=16;o;o>>=1) s += __shfl_xor_sync(0xffffffffu, s, o);
            float inv = 1.f/s;
            sAtt[r*SRCs + lane] = e0*inv;
            if (lane < 8) sAtt[r*SRCs + 32 + lane] = e1*inv;
        }
        __syncthreads();

        // ctx packed (duplicated)
        {
            int j = tid & 255, rr = tid >> 8;
            #pragma unroll
            for (int q = 0; q < 2; q++) {
                int r = rr*2 + q;
                float cx = 0.f;
                #pragma unroll 8
                for (int s=0;s<SRCs;s++) cx += sAtt[r*SRCs + s]*sMem[(r*SRCs + s)*Dd + j];
                sCatP[j*4 + r] = cx;
            }
        }
        __syncthreads();

        // soa = tanh(cat @ Wc + bc); duplicated; 4-way k-split
        {
            const int sp = tid >> 7;
            const int cg = tid & 127;
            const int c0 = cg*2;
            const int kb = sp*128;
            ull a01[2] = {0,0}, a23[2] = {0,0};
            {
                float2 wA[8], wB[8];
                #pragma unroll
                for (int u=0;u<8;u++) wA[u] = *(const float2*)(Wc + (size_t)(kb+u)*Dd + c0);
                for (int it = 0; it < 8; ++it) {
                    int kA = kb + it*16;
                    #pragma unroll
                    for (int u=0;u<8;u++) wB[u] = *(const float2*)(Wc + (size_t)(kA+8+u)*Dd + c0);
                    #pragma unroll
                    for (int u=0;u<8;u++) {
                        ull x01 = *(const ull*)(sCatP + (kA+u)*4);
                        ull x23 = *(const ull*)(sCatP + (kA+u)*4 + 2);
                        ull p0 = pk2(wA[u].x,wA[u].x), p1 = pk2(wA[u].y,wA[u].y);
                        FMA2(a01[0],x01,p0); FMA2(a23[0],x23,p0);
                        FMA2(a01[1],x01,p1); FMA2(a23[1],x23,p1);
                    }
                    int kAn = (it < 7) ? kA + 16 : kb;
                    #pragma unroll
                    for (int u=0;u<8;u++) wA[u] = *(const float2*)(Wc + (size_t)(kAn+u)*Dd + c0);
                    #pragma unroll
                    for (int u=0;u<8;u++) {
                        ull x01 = *(const ull*)(sCatP + (kA+8+u)*4);
                        ull x23 = *(const ull*)(sCatP + (kA+8+u)*4 + 2);
                        ull p0 = pk2(wB[u].x,wB[u].x), p1 = pk2(wB[u].y,wB[u].y);
                        FMA2(a01[0],x01,p0); FMA2(a23[0],x23,p0);
                        FMA2(a01[1],x01,p1); FMA2(a23[1],x23,p1);
                    }
                }
            }
            if (sp > 0) {
                float* scr = sGx + (sp-1)*1024;
                #pragma unroll
                for (int j=0;j<2;j++) {
                    float2 p01 = up2(a01[j]), p23 = up2(a23[j]);
                    scr[(c0+j)*4+0] = p01.x; scr[(c0+j)*4+1] = p01.y;
                    scr[(c0+j)*4+2] = p23.x; scr[(c0+j)*4+3] = p23.y;
                }
            }
            __syncthreads();
            if (sp == 0) {
                #pragma unroll
                for (int j=0;j<2;j++) {
                    float2 p01 = up2(a01[j]), p23 = up2(a23[j]);
                    float v[4] = {p01.x, p01.y, p23.x, p23.y};
                    float bcv = bc[c0+j];
                    #pragma unroll
                    for (int r=0;r<4;r++) {
                        float sum = v[r] + sGx[0*1024+(c0+j)*4+r]
                                         + sGx[1*1024+(c0+j)*4+r]
                                         + sGx[2*1024+(c0+j)*4+r] + bcv;
                        float s = tanhf(sum);
                        sSoaP[(c0+j)*4+r] = s;
                        if (h == 0) sTs[r*256+c0+j] = tanhf(sTs[r*256+c0+j] + s);
                    }
                }
            }
            __syncthreads();
        }

        // logits half: cols [h*1000, h*1000+1000); argmax
        {
            ull best[RPB] = {0ull,0ull,0ull,0ull};
            if (tid < 500) {
                int c0 = h*1000 + tid*2;
                ull a01[2] = {0,0}, a23[2] = {0,0};
                float2 wA[8], wB[8];
                #pragma unroll
                for (int u=0;u<8;u++) wA[u] = *(const float2*)(Wsym + (size_t)u*Vv + c0);
                for (int it = 0; it < 16; ++it) {
                    int kA = it*16;
                    #pragma unroll
                    for (int u=0;u<8;u++) wB[u] = *(const float2*)(Wsym + (size_t)(kA+8+u)*Vv + c0);
                    #pragma unroll
                    for (int u=0;u<8;u++) {
                        ull x01 = *(const ull*)(sSoaP + (kA+u)*4);
                        ull x23 = *(const ull*)(sSoaP + (kA+u)*4 + 2);
                        ull p0 = pk2(wA[u].x,wA[u].x), p1 = pk2(wA[u].y,wA[u].y);
                        FMA2(a01[0],x01,p0); FMA2(a23[0],x23,p0);
                        FMA2(a01[1],x01,p1); FMA2(a23[1],x23,p1);
                    }
                    int kAn = (it < 15) ? kA + 16 : 0;
                    #pragma unroll
                    for (int u=0;u<8;u++) wA[u] = *(const float2*)(Wsym + (size_t)(kAn+u)*Vv + c0);
                    #pragma unroll
                    for (int u=0;u<8;u++) {
                        ull x01 = *(const ull*)(sSoaP + (kA+8+u)*4);
                        ull x23 = *(const ull*)(sSoaP + (kA+8+u)*4 + 2);
                        ull p0 = pk2(wB[u].x,wB[u].x), p1 = pk2(wB[u].y,wB[u].y);
                        FMA2(a01[0],x01,p0); FMA2(a23[0],x23,p0);
                        FMA2(a01[1],x01,p1); FMA2(a23[1],x23,p1);
                    }
                }
                float2 bs = *(const float2*)(bsym + c0);
                float vb[2] = {bs.x, bs.y};
                float vr[RPB][2];
                #pragma unroll
                for (int j=0;j<2;j++) {
                    float2 p01 = up2(a01[j]), p23 = up2(a23[j]);
                    vr[0][j] = p01.x + vb[j];
                    vr[1][j] = p01.y + vb[j];
                    vr[2][j] = p23.x + vb[j];
                    vr[3][j] = p23.y + vb[j];
                }
                #pragma unroll
                for (int r=0;r<RPB;r++) {
                    int row = t*Bb + b0 + r;
                    uchar2 wm = *(const uchar2*)(d_w + (size_t)row*Vv + c0);
                    unsigned char wmv[2] = {wm.x, wm.y};
                    float2 st;
                    float* stp = &st.x;
                    #pragma unroll
                    for (int j=0;j<2;j++) {
                        float v = vr[r][j];
                        if (!wmv[j]) v += LT;
                        stp[j] = v;
                        ull key = ((ull)f2mono(v) << 32) | (0xFFFFFFFFu - (unsigned)(c0 + j));
                        if (key > best[r]) best[r] = key;
                    }
                    *(float2*)(d_clog + (size_t)row*Vv + c0) = st;
                }
            }
            #pragma unroll
            for (int r=0;r<RPB;r++) {
                ull bv = best[r];
                #pragma unroll
                for (int o=16;o;o>>=1) {
                    ull x = __shfl_xor_sync(0xffffffffu, bv, o);
                    if (x > bv) bv = x;
                }
                if (lane == 0 && bv) atomicMax(&sArg[r], bv);
            }
        }
        __syncthreads();
        if (tid < RPB) atomicMax(&d_pairArg[(p*SEQs + t)*RPB + tid], sArg[tid]);
        psync(p, ++gen);
        if (tid < RPB) {
            ull k = *((volatile ull*)&d_pairArg[(p*SEQs + t)*RPB + tid]);
            sPrev[tid] = (int)(0xFFFFFFFFu - (unsigned)(k & 0xFFFFFFFFull));
            sArg[tid] = 0ull;
        }
        __syncthreads();
    }

    if (h == 0) {
        for (int i = tid; i < RPB*Dd; i += THR)
            d_ts[b0*Dd + i] = sTs[i];
    }
}

// ============================================================================
// k_tail: per-batch lse + opts + topo + prepA. grid=256.
// ============================================================================
__global__ __launch_bounds__(256) void k_tail(const int* __restrict__ gg,
                                              const float* __restrict__ emb,
                                              float* __restrict__ out)
{
    const int b = blockIdx.x;
    const int tid = threadIdx.x;
    const int lane = tid & 31, warp = tid >> 5;
    __shared__ float sLse[SEQs];
    __shared__ float sVals[OPTo*SEQs];
    __shared__ float sSol[OPTo];
    __shared__ int   sBest;
    __shared__ int   sSym[SEQs];

    for (int t = warp; t < SEQs; t += 8) {
        const float* row = d_clog + ((size_t)t*Bb + b)*Vv;
        float m = -1e30f;
        for (int v = lane; v < Vv; v += 32) m = fmaxf(m, row[v]);
        #pragma unroll
        for (int o=16;o;o>>=1) m = fmaxf(m, __shfl_xor_sync(0xffffffffu, m, o));
        float s = 0.f;
        for (int v = lane; v < Vv; v += 32) s += expf(row[v]-m);
        #pragma unroll
        for (int o=16;o;o>>=1) s += __shfl_xor_sync(0xffffffffu, s, o);
        if (lane == 0) sLse[t] = m + logf(s);
    }
    __syncthreads();
    if (tid < OPTo*SEQs) {
        int o = tid / SEQs, t = tid % SEQs;
        int base = ((b*OPTo + o)*4)*SEQs + t;
        int m = gg[base + 3*SEQs];
        float v = 0.f;
        if (m) {
            int sym = gg[base];
            v = logf(expf(d_clog[((size_t)t*Bb + b)*Vv + sym] - sLse[t]) + 1e-13f);
        }
        sVals[tid] = v;
    }
    __syncthreads();
    if (tid < OPTo) {
        float s = 0.f;
        #pragma unroll
        for (int t=0;t<SEQs;t++) s += sVals[tid*SEQs + t];
        sSol[tid] = s;
        out[OFF_OPT + b*OPTo + tid] = s;
    }
    __syncthreads();
    if (tid == 0) {
        int bi = 0; float bv = sSol[0];
        for (int o=1;o<OPTo;o++) if (sSol[o] > bv) { bv = sSol[o]; bi = o; }
        sBest = bi;
    }
    __syncthreads();
    if (tid < 4*SEQs) {
        int c = tid / SEQs, s = tid % SEQs;
        int val = gg[((b*OPTo + sBest)*4 + c)*SEQs + s];
        out[OFF_TOPO + c*(Bb*SEQs) + b*SEQs + s] = (float)val;
        if (c == 0) { sSym[s] = val; d_sym[b*SEQs + s] = val; }
    }
    __syncthreads();
    for (int i = tid; i < SEQs*512; i += 256) {
        int s = i >> 9, k = i & 511;
        float v = (k < Dd) ? emb[(size_t)sSym[s]*Dd + k] : d_ts[b*Dd + (k - Dd)];
        d_Ahi[((size_t)b*SEQs + s)*512 + k] = __float2bfloat16(v);
    }
}

// ---------------- exact_logit GEMM: bf16 mma + ldmatrix, 128x128x32, 2-buf --
#define MMA16816(d, a, b) asm volatile( \
    "mma.sync.aligned.m16n8k16.row.col.f32.bf16.bf16.f32 " \
    "{%0,%1,%2,%3}, {%4,%5,%6,%7}, {%8,%9}, {%0,%1,%2,%3};\n" \
    : "+f"(d[0]), "+f"(d[1]), "+f"(d[2]), "+f"(d[3]) \
    : "r"(a[0]), "r"(a[1]), "r"(a[2]), "r"(a[3]), "r"(b[0]), "r"(b[1]))

#define LDSM4(r0,r1,r2,r3,addr) asm volatile( \
    "ldmatrix.sync.aligned.m8n8.x4.shared.b16 {%0,%1,%2,%3}, [%4];" \
    : "=r"(r0), "=r"(r1), "=r"(r2), "=r"(r3) : "r"(addr))

#define LDSM2(r0,r1,addr) asm volatile( \
    "ldmatrix.sync.aligned.m8n8.x2.shared.b16 {%0,%1}, [%2];" \
    : "=r"(r0), "=r"(r1) : "r"(addr))

#define XSTR 40

__global__ __launch_bounds__(256) void k_exact(const float* __restrict__ btok,
                                               const float* __restrict__ tok,
                                               float* __restrict__ out) {
    __shared__ __nv_bfloat16 sA[2][128*XSTR], sB[2][128*XSTR];
    int tid = threadIdx.x;
    int m0 = blockIdx.y*128, n0 = blockIdx.x*128;
    int lane = tid & 31, warp = tid >> 5;
    int wm = warp >> 2, wn = warp & 3;
    int g = lane >> 2, tq = lane & 3;
    float acc[4][4][4];
    #pragma unroll
    for (int i=0;i<4;i++) {
        #pragma unroll
        for (int j=0;j<4;j++) {
            #pragma unroll
            for (int q=0;q<4;q++) acc[i][j][q] = 0.f;
        }
    }

    int row = tid >> 1;
    int kh  = (tid & 1) << 4;
    int nr  = n0 + row;
    const bool nok = (nr < VTt);

    // ldmatrix per-lane base coordinates
    const uint32_t aBase = (uint32_t)__cvta_generic_to_shared(&sA[0][0]);
    const uint32_t bBase = (uint32_t)__cvta_generic_to_shared(&sB[0][0]);
    const int rA  = wm*64 + ((lane>>3)&1)*8 + (lane&7);
    const int cAo = ((lane>>4)&1)*8;
    const int rB  = wn*32 + (lane&7);
    const int cBo = ((lane>>3)&1)*8;

    uint4 ra0, ra1, rb0, rb1;
    const uint4 z0 = make_uint4(0,0,0,0);

    {
        const uint4* p = (const uint4*)(d_Ahi + (size_t)(m0+row)*512 + kh);
        ra0 = p[0]; ra1 = p[1];
        rb0 = z0; rb1 = z0;
        if (nok) {
            const uint4* q = (const uint4*)(d_WhiT + (size_t)nr*512 + kh);
            rb0 = q[0]; rb1 = q[1];
        }
    }
    *(uint4*)&sA[0][row*XSTR + kh]     = ra0;
    *(uint4*)&sA[0][row*XSTR + kh + 8] = ra1;
    *(uint4*)&sB[0][row*XSTR + kh]     = rb0;
    *(uint4*)&sB[0][row*XSTR + kh + 8] = rb1;
    __syncthreads();

    int buf = 0;
    for (int k0 = 0; k0 < 512; k0 += 32) {
        int nxt = k0 + 32;
        if (nxt < 512) {
            const uint4* p = (const uint4*)(d_Ahi + (size_t)(m0+row)*512 + nxt + kh);
            ra0 = p[0]; ra1 = p[1];
            rb0 = z0; rb1 = z0;
            if (nok) {
                const uint4* q = (const uint4*)(d_WhiT + (size_t)nr*512 + nxt + kh);
                rb0 = q[0]; rb1 = q[1];
            }
        }
        const uint32_t aBuf = aBase + (unsigned)buf*(128*XSTR*2);
        const uint32_t bBuf = bBase + (unsigned)buf*(128*XSTR*2);
        #pragma unroll
        for (int ks = 0; ks < 2; ks++) {
            int kb = ks*16;
            uint32_t ah[4][4];
            #pragma unroll
            for (int mi=0;mi<4;mi++) {
                uint32_t ad = aBuf + (unsigned)(((rA + mi*16)*XSTR + kb + cAo)*2);
                LDSM4(ah[mi][0], ah[mi][1], ah[mi][2], ah[mi][3], ad);
            }
            uint32_t bh[4][2];
            #pragma unroll
            for (int ni=0;ni<4;ni++) {
                uint32_t bd = bBuf + (unsigned)(((rB + ni*8)*XSTR + kb + cBo)*2);
                LDSM2(bh[ni][0], bh[ni][1], bd);
            }
            #pragma unroll
            for (int mi=0;mi<4;mi++) {
                #pragma unroll
                for (int ni=0;ni<4;ni++) {
                    MMA16816(acc[mi][ni], ah[mi], bh[ni]);
                }
            }
        }
        if (nxt < 512) {
            *(uint4*)&sA[buf^1][row*XSTR + kh]     = ra0;
            *(uint4*)&sA[buf^1][row*XSTR + kh + 8] = ra1;
            *(uint4*)&sB[buf^1][row*XSTR + kh]     = rb0;
            *(uint4*)&sB[buf^1][row*XSTR + kh + 8] = rb1;
            __syncthreads();
            buf ^= 1;
        }
    }

    const float LT = logf(1e-13f);
    #pragma unroll
    for (int mi=0;mi<4;mi++) {
        int r0 = m0 + wm*64 + mi*16 + g;
        int s0 = d_sym[r0];
        int s1 = d_sym[r0 + 8];
        #pragma unroll
        for (int ni=0;ni<4;ni++) {
            int c0 = n0 + wn*32 + ni*8 + tq*2;
            if (c0 < VTt) {
                float b0 = btok[c0];
                out[OFF_EX + (size_t)r0*VTt + c0]     = acc[mi][ni][0] + b0 + (tok[(size_t)s0*VTt + c0] > 0.f ? 0.f : LT);
                out[OFF_EX + (size_t)(r0+8)*VTt + c0] = acc[mi][ni][2] + b0 + (tok[(size_t)s1*VTt + c0] > 0.f ? 0.f : LT);
            }
            if (c0 + 1 < VTt) {
                float b1 = btok[c0+1];
                out[OFF_EX + (size_t)r0*VTt + c0+1]     = acc[mi][ni][1] + b1 + (tok[(size_t)s0*VTt + c0+1] > 0.f ? 0.f : LT);
                out[OFF_EX + (size_t)(r0+8)*VTt + c0+1] = acc[mi][ni][3] + b1 + (tok[(size_t)s1*VTt + c0+1] > 0.f ? 0.f : LT);
            }
        }
    }
}

// ---------------- host launcher ----------------
extern "C" void kernel_launch(void* const* d_in, const int* in_sizes, int n_in,
                              void* d_out, int out_size) {
    const int*   lhs   = (const int*)d_in[0];
    const int*   lmask = (const int*)d_in[1];
    const float* ts0   = (const float*)d_in[2];
    const int*   gg    = (const int*)d_in[3];
    const float* emb   = (const float*)d_in[4];
    const float* mem   = (const float*)d_in[5];
    const float* Wx    = (const float*)d_in[6];
    const float* Wh    = (const float*)d_in[7];
    const float* bx    = (const float*)d_in[8];
    const float* bh    = (const float*)d_in[9];
    const float* Wc    = (const float*)d_in[10];
    const float* bc    = (const float*)d_in[11];
    const float* Wsym  = (const float*)d_in[12];
    const float* bsym  = (const float*)d_in[13];
    const float* Wtok  = (const float*)d_in[14];
    const float* btok  = (const float*)d_in[15];
    const float* tok   = (const float*)d_in[16];
    float* out = (float*)d_out;

    static bool attr_set = false;
    if (!attr_set) {
        cudaFuncSetAttribute(k_steps, cudaFuncAttributeMaxDynamicSharedMemorySize, SM_BYTES);
        attr_set = true;
    }

    k_w<<<SEQs*Bb, 64>>>(gg);
    k_prepW<<<5008, 256>>>(Wtok);
    k_copy<<<642, 256>>>(lhs, lmask, gg, out);
    k_steps<<<GSTEP, THR, SM_BYTES>>>(lhs, ts0, emb, mem, Wx, bx, Wh, bh, Wc, bc, Wsym, bsym);
    k_tail<<<Bb, 256>>>(gg, emb, out);
    k_exact<<<dim3((VTt+127)/128, (Bb*SEQs)/128), 256>>>(btok, tok, out);
}